// round 2
// baseline (speedup 1.0000x reference)
#include <cuda_runtime.h>

// ---------------------------------------------------------------------------
// CrossAtt fp32 for GB300 — round 2: double-buffered BK=16 SGEMM.
// Shapes (fixed): B=8, H=W=64 -> N=4096, DIM=640, HEADS=8, SEG=128, CH=64.
// ---------------------------------------------------------------------------

#define RSQ_BN 0.9999950000374997f      // 1/sqrt(1+1e-5)
#define SCALE_V 0.11180339887498949f    // (640/8)^-0.5
#define LN_EPS 1e-5f

__device__ __forceinline__ float hsw(float x) {
    return x * fminf(fmaxf(x + 3.f, 0.f), 6.f) * (1.f / 6.f);
}

// ---------------- scratch (single bss array, no allocations) ---------------
static __device__ __align__(256) float g_scratch[138682368ULL];

// ---------------------------------------------------------------------------
// Tiled SGEMM: C[M,N] = A[M,K] * W[N,K]^T  (W row-major (N,K))
// BM=BN=128, BK=16, 256 threads, 8x8 per thread, double-buffered smem with
// register-staged global prefetch.
// MODE 0: C[m*ldc+n] = acc
// MODE 1: C[m*ldc+n] = acc + p2[n]                      (bias)
// MODE 2: v = hswish(acc * (p1[n]*RSQ_BN) + p2[n]);     (BN eval + hardswish)
//         scatter to head buffer C[((b*8+h)*4096+nn)*64+cc]
// Requires M%128==0, N%128==0, K%16==0.
// ---------------------------------------------------------------------------
template <int MODE>
__global__ void __launch_bounds__(256) sgemm_k(
    const float* __restrict__ A, int lda,
    const float* __restrict__ W,
    float* __restrict__ C, int ldc,
    int M, int N, int K,
    const float* __restrict__ p1, const float* __restrict__ p2, int headBase)
{
    __shared__ float As[2][16][128];
    __shared__ float Bs[2][16][128];

    const int tid  = threadIdx.x;
    const int lrow = tid & 127;            // row within tile (m or n)
    const int lk   = (tid >> 7) << 3;      // 0 or 8 (k offset)

    const float* Ap = A + ((long)blockIdx.y * 128 + lrow) * (long)lda + lk;
    const float* Wp = W + ((long)blockIdx.x * 128 + lrow) * (long)K + lk;

    const int tr = tid >> 4;   // 0..15
    const int tc = tid & 15;   // 0..15

    float acc[8][8];
#pragma unroll
    for (int i = 0; i < 8; i++)
#pragma unroll
        for (int j = 0; j < 8; j++) acc[i][j] = 0.f;

    float ar[8], br[8];

#define LD8(dst, ptr)                                                         \
    {                                                                         \
        float4 t0 = *reinterpret_cast<const float4*>(ptr);                    \
        float4 t1 = *reinterpret_cast<const float4*>((ptr) + 4);              \
        dst[0] = t0.x; dst[1] = t0.y; dst[2] = t0.z; dst[3] = t0.w;           \
        dst[4] = t1.x; dst[5] = t1.y; dst[6] = t1.z; dst[7] = t1.w;           \
    }

#define ST_SMEM(bf)                                                           \
    {                                                                         \
        _Pragma("unroll")                                                     \
        for (int i = 0; i < 8; i++) {                                         \
            As[bf][lk + i][lrow] = ar[i];                                     \
            Bs[bf][lk + i][lrow] = br[i];                                     \
        }                                                                     \
    }

#define COMPUTE(bf)                                                           \
    {                                                                         \
        _Pragma("unroll")                                                     \
        for (int k = 0; k < 16; k++) {                                        \
            float4 x0 = *reinterpret_cast<const float4*>(&As[bf][k][tr * 8]); \
            float4 x1 = *reinterpret_cast<const float4*>(&As[bf][k][tr * 8 + 4]); \
            float4 y0 = *reinterpret_cast<const float4*>(&Bs[bf][k][tc * 8]); \
            float4 y1 = *reinterpret_cast<const float4*>(&Bs[bf][k][tc * 8 + 4]); \
            float xa[8] = {x0.x, x0.y, x0.z, x0.w, x1.x, x1.y, x1.z, x1.w};   \
            float ya[8] = {y0.x, y0.y, y0.z, y0.w, y1.x, y1.y, y1.z, y1.w};   \
            _Pragma("unroll")                                                 \
            for (int i = 0; i < 8; i++)                                       \
                _Pragma("unroll")                                             \
                for (int j = 0; j < 8; j++)                                   \
                    acc[i][j] = fmaf(xa[i], ya[j], acc[i][j]);                \
        }                                                                     \
    }

    // prologue: tile 0
    LD8(ar, Ap);
    LD8(br, Wp);
    int buf = 0;
    ST_SMEM(0);
    __syncthreads();

    for (int k0 = 16; k0 < K; k0 += 16) {
        LD8(ar, Ap + k0);          // prefetch next tile (overlaps compute)
        LD8(br, Wp + k0);
        COMPUTE(buf);
        buf ^= 1;
        ST_SMEM(buf);
        __syncthreads();
    }
    COMPUTE(buf);

#undef LD8
#undef ST_SMEM
#undef COMPUTE

    const int m0 = blockIdx.y * 128 + tr * 8;
    const int n0 = blockIdx.x * 128 + tc * 8;
#pragma unroll
    for (int i = 0; i < 8; i++) {
        const int m = m0 + i;
#pragma unroll
        for (int j = 0; j < 8; j++) {
            const int n = n0 + j;
            float v = acc[i][j];
            if (MODE == 0) {
                C[(long)m * ldc + n] = v;
            } else if (MODE == 1) {
                C[(long)m * ldc + n] = v + p2[n];
            } else {
                v = v * (p1[n] * RSQ_BN) + p2[n];
                v = hsw(v);
                const int b = m >> 12, nn = m & 4095;
                const int h = headBase + (n >> 6), cc = n & 63;
                C[((((long)b * 8 + h) * 4096) + nn) * 64 + cc] = v;
            }
        }
    }
}

// ---------------------------------------------------------------------------
// seg0 branch: hardswish(BN(x)) -> head layout (heads 0,1)
// ---------------------------------------------------------------------------
__global__ void seg0_k(const float* __restrict__ in, int inRow,
                       float* __restrict__ hb,
                       const float* __restrict__ g, const float* __restrict__ bb)
{
    const int c = threadIdx.x;                       // 0..127
    const int n = blockIdx.x * blockDim.y + threadIdx.y;
    const int b = blockIdx.y;
    float v = in[((long)b * 4096 + n) * (long)inRow + c];
    v = v * (g[c] * RSQ_BN) + bb[c];
    v = hsw(v);
    const int h = c >> 6, cc = c & 63;
    hb[(((long)b * 8 + h) * 4096 + n) * 64 + cc] = v;
}

// ---------------------------------------------------------------------------
// Generic depthwise conv on a 64x64 image, channel-last rows.
// ---------------------------------------------------------------------------
template <int KS>
__global__ void dwconv_k(const float* __restrict__ in, long inOuter, long inInner, int inRow,
                         float* __restrict__ out, long outOuter, long outInner,
                         const float* __restrict__ w, int C, int nh)
{
    extern __shared__ float ws[];
    const int batch = blockIdx.y;
    const int outer = batch / nh, inner = batch % nh;
    const float* ip = in + outer * inOuter + inner * inInner;
    float* op = out + outer * outOuter + inner * outInner;
    const float* wp = w + (long)inner * C * KS * KS;

    const int nthr = blockDim.x * blockDim.y;
    const int tid = threadIdx.y * blockDim.x + threadIdx.x;
    for (int i = tid; i < C * KS * KS; i += nthr) ws[i] = wp[i];
    __syncthreads();

    const int c = threadIdx.x;
    const int pix = blockIdx.x * blockDim.y + threadIdx.y;
    const int y = pix >> 6, x = pix & 63;
    const int P = KS / 2;
    float acc = 0.f;
#pragma unroll
    for (int dy = 0; dy < KS; dy++) {
        const int yy = y + dy - P;
        if (yy < 0 || yy > 63) continue;
#pragma unroll
        for (int dx = 0; dx < KS; dx++) {
            const int xx = x + dx - P;
            if (xx < 0 || xx > 63) continue;
            acc = fmaf(ws[c * KS * KS + dy * KS + dx],
                       ip[(long)(yy * 64 + xx) * inRow + c], acc);
        }
    }
    op[(long)pix * C + c] = acc;
}

// ---------------------------------------------------------------------------
// Softmax stats over tokens (axis N) per (b,h,c); zeroes kTv accumulator.
// ---------------------------------------------------------------------------
__global__ void softstats_k(const float* __restrict__ Kh,
                            float* __restrict__ mx, float* __restrict__ sm,
                            float* __restrict__ ktv)
{
    const int bh = blockIdx.x;
    const int c  = threadIdx.x & 63;
    const int sl = threadIdx.x >> 6;    // 0..7
    const float* kp = Kh + (long)bh * 4096 * 64;

    float* kz = ktv + (long)bh * 4096;
    for (int i = threadIdx.x; i < 4096; i += 512) kz[i] = 0.f;

    float m = -1e30f;
    for (int j = 0; j < 512; j++) {
        const int n = sl * 512 + j;
        m = fmaxf(m, kp[(long)n * 64 + c]);
    }
    __shared__ float red[512];
    __shared__ float red2[512];
    red[threadIdx.x] = m;
    __syncthreads();
    if (sl == 0) {
        for (int s = 1; s < 8; s++) m = fmaxf(m, red[s * 64 + c]);
        red[c] = m;
    }
    __syncthreads();
    m = red[c];

    float s = 0.f;
    for (int j = 0; j < 512; j++) {
        const int n = sl * 512 + j;
        s += __expf(kp[(long)n * 64 + c] - m);
    }
    red2[threadIdx.x] = s;
    __syncthreads();
    if (sl == 0) {
        for (int ss = 1; ss < 8; ss++) s += red2[ss * 64 + c];
        mx[bh * 64 + c] = m;
        sm[bh * 64 + c] = s;
    }
}

// ---------------------------------------------------------------------------
// kTv[c1,c2] += sum_n softmax(k)[n,c1] * v[n,c2], split over 8 n-chunks.
// ---------------------------------------------------------------------------
__global__ void ktv_k(const float* __restrict__ Kh, const float* __restrict__ Vh,
                      const float* __restrict__ mx, const float* __restrict__ sm,
                      float* __restrict__ ktv)
{
    const int bh = blockIdx.y;
    const int chunk = blockIdx.x;
    const int tid = threadIdx.x;
    __shared__ float sk[4][64];
    __shared__ float sv[4][64];

    const float* kp = Kh + (long)bh * 4096 * 64;
    const float* vp = Vh + (long)bh * 4096 * 64;
    const int lc = tid & 63, lr = tid >> 6;
    const float lm = mx[bh * 64 + lc];
    const float lrs = 1.f / sm[bh * 64 + lc];

    const int i0 = (tid & 15) * 4;   // c1 base
    const int j0 = (tid >> 4) * 4;   // c2 base
    float acc[4][4] = {};

    const int nend = chunk * 512 + 512;
    for (int n0 = chunk * 512; n0 < nend; n0 += 4) {
        sk[lr][lc] = __expf(kp[(long)(n0 + lr) * 64 + lc] - lm) * lrs;
        sv[lr][lc] = vp[(long)(n0 + lr) * 64 + lc];
        __syncthreads();
#pragma unroll
        for (int r = 0; r < 4; r++) {
            float a[4], bv[4];
#pragma unroll
            for (int i = 0; i < 4; i++) a[i] = sk[r][i0 + i];
#pragma unroll
            for (int j = 0; j < 4; j++) bv[j] = sv[r][j0 + j];
#pragma unroll
            for (int i = 0; i < 4; i++)
#pragma unroll
                for (int j = 0; j < 4; j++) acc[i][j] = fmaf(a[i], bv[j], acc[i][j]);
        }
        __syncthreads();
    }
    float* kp2 = ktv + (long)bh * 4096;
#pragma unroll
    for (int i = 0; i < 4; i++)
#pragma unroll
        for (int j = 0; j < 4; j++)
            atomicAdd(&kp2[(i0 + i) * 64 + (j0 + j)], acc[i][j]);
}

// ---------------------------------------------------------------------------
// eff = q @ kTv; o = SCALE*eff + q * crpe -> obuf[b][n][h*64+c2]
// ---------------------------------------------------------------------------
__global__ void eff_k(const float* __restrict__ Qh, const float* __restrict__ ktv,
                      const float* __restrict__ crpe, float* __restrict__ obuf)
{
    const int bh = blockIdx.y;
    const int b = bh >> 3, h = bh & 7;
    const int n0 = blockIdx.x * 64;
    const int tid = threadIdx.x;

    __shared__ float skt[64][64];
    __shared__ float sq[64][65];

    const float* ktp = ktv + (long)bh * 4096;
    const float* qp  = Qh + ((long)bh * 4096 + n0) * 64;
    for (int i = tid; i < 4096; i += 256) {
        skt[i >> 6][i & 63] = ktp[i];
        sq[i >> 6][i & 63]  = qp[i];
    }
    __syncthreads();

    const int i0 = (tid & 15) * 4;   // n offset in tile
    const int j0 = (tid >> 4) * 4;   // c2 offset
    float acc[4][4] = {};
#pragma unroll
    for (int c1 = 0; c1 < 64; c1++) {
        float a[4], bv[4];
#pragma unroll
        for (int i = 0; i < 4; i++) a[i] = sq[i0 + i][c1];
#pragma unroll
        for (int j = 0; j < 4; j++) bv[j] = skt[c1][j0 + j];
#pragma unroll
        for (int i = 0; i < 4; i++)
#pragma unroll
            for (int j = 0; j < 4; j++) acc[i][j] = fmaf(a[i], bv[j], acc[i][j]);
    }

    const float* crp = crpe + ((long)bh * 4096 + n0) * 64;
#pragma unroll
    for (int i = 0; i < 4; i++) {
        const int n = n0 + i0 + i;
#pragma unroll
        for (int j = 0; j < 4; j++) {
            const int c2 = j0 + j;
            const float q = sq[i0 + i][c2];
            const float cr = q * crp[(long)(i0 + i) * 64 + c2];
            obuf[((long)b * 4096 + n) * 640 + h * 64 + c2] = SCALE_V * acc[i][j] + cr;
        }
    }
}

// ---------------------------------------------------------------------------
// LayerNorm(128) + hardswish, write (or add) into obuf channels [512,640).
// ---------------------------------------------------------------------------
__global__ void ln_k(const float* __restrict__ in,
                     const float* __restrict__ g, const float* __restrict__ bb,
                     float* __restrict__ obuf, int addMode)
{
    const int row  = blockIdx.x * 8 + (threadIdx.x >> 5);
    const int lane = threadIdx.x & 31;
    const float* ip = in + (long)row * 128;
    float4 v = reinterpret_cast<const float4*>(ip)[lane];
    float s  = v.x + v.y + v.z + v.w;
    float sq = v.x * v.x + v.y * v.y + v.z * v.z + v.w * v.w;
#pragma unroll
    for (int o = 16; o > 0; o >>= 1) {
        s  += __shfl_xor_sync(0xffffffffu, s, o);
        sq += __shfl_xor_sync(0xffffffffu, sq, o);
    }
    const float m = s * (1.f / 128.f);
    const float var = sq * (1.f / 128.f) - m * m;
    const float r = rsqrtf(var + LN_EPS);
    const int c0 = lane * 4;
    float vals[4] = {v.x, v.y, v.z, v.w};
    float* op = obuf + (long)row * 640 + 512 + c0;
    float out[4];
#pragma unroll
    for (int i = 0; i < 4; i++) {
        float vv = (vals[i] - m) * r * g[c0 + i] + bb[c0 + i];
        vv = hsw(vv);
        out[i] = addMode ? (op[i] + vv) : vv;
    }
    *reinterpret_cast<float4*>(op) = make_float4(out[0], out[1], out[2], out[3]);
}

// ---------------------------------------------------------------------------
// One aggregator stream: seg0 + 3 conv branches (+ optional local branch).
// ---------------------------------------------------------------------------
static void run_stream(const float* base, int rowStride,
                       const float* dw3, const float* dw5, const float* dw7,
                       const float* pw, const float* bng, const float* bnb,
                       float* headbuf, float* tmp, float* locraw, float* obuf,
                       bool doLoc, const float* lng, const float* lnb, int locAdd)
{
    const long inOuter = 4096L * rowStride;
    const long outO = 4096L * 128;

    seg0_k<<<dim3(2048, 8), dim3(128, 2)>>>(base, rowStride, headbuf, bng, bnb);

    dwconv_k<3><<<dim3(2048, 8), dim3(128, 2), 128 * 9 * 4>>>(
        base + 128, inOuter, 0, rowStride, tmp, outO, 0, dw3 + 128 * 9, 128, 1);
    sgemm_k<2><<<dim3(1, 256), 256>>>(tmp, 128, pw + 16384, headbuf, 0,
                                      32768, 128, 128, bng + 128, bnb + 128, 2);
    dwconv_k<5><<<dim3(2048, 8), dim3(128, 2), 128 * 25 * 4>>>(
        base + 256, inOuter, 0, rowStride, tmp, outO, 0, dw5, 128, 1);
    sgemm_k<2><<<dim3(1, 256), 256>>>(tmp, 128, pw + 2 * 16384, headbuf, 0,
                                      32768, 128, 128, bng + 256, bnb + 256, 4);
    dwconv_k<7><<<dim3(2048, 8), dim3(128, 2), 128 * 49 * 4>>>(
        base + 384, inOuter, 0, rowStride, tmp, outO, 0, dw7, 128, 1);
    sgemm_k<2><<<dim3(1, 256), 256>>>(tmp, 128, pw + 3 * 16384, headbuf, 0,
                                      32768, 128, 128, bng + 384, bnb + 384, 6);

    if (doLoc) {
        dwconv_k<3><<<dim3(2048, 8), dim3(128, 2), 128 * 9 * 4>>>(
            base + 512, inOuter, 0, rowStride, tmp, outO, 0, dw3, 128, 1);
        sgemm_k<0><<<dim3(1, 256), 256>>>(tmp, 128, pw, locraw, 128,
                                          32768, 128, 128, nullptr, nullptr, 0);
        ln_k<<<4096, 256>>>(locraw, lng, lnb, obuf, locAdd);
    }
}

// ---------------------------------------------------------------------------
extern "C" void kernel_launch(void* const* d_in, const int* in_sizes, int n_in,
                              void* d_out, int out_size)
{
    (void)in_sizes; (void)n_in; (void)out_size;
    const float* x        = (const float*)d_in[0];
    const float* y        = (const float*)d_in[1];
    const float* kv_w     = (const float*)d_in[2];
    const float* proj_w   = (const float*)d_in[3];
    const float* proj_b   = (const float*)d_in[4];
    const float* crpe_w3  = (const float*)d_in[5];
    const float* crpe_w5  = (const float*)d_in[6];
    const float* crpe_w7  = (const float*)d_in[7];
    const float* aq_dw3   = (const float*)d_in[8];
    const float* aq_dw5   = (const float*)d_in[9];
    const float* aq_dw7   = (const float*)d_in[10];
    const float* aq_pw    = (const float*)d_in[11];
    const float* aq_ln_g  = (const float*)d_in[12];
    const float* aq_ln_b  = (const float*)d_in[13];
    const float* aq_bn_g  = (const float*)d_in[14];
    const float* aq_bn_b  = (const float*)d_in[15];
    const float* akv_dw3  = (const float*)d_in[16];
    const float* akv_dw5  = (const float*)d_in[17];
    const float* akv_dw7  = (const float*)d_in[18];
    const float* akv_pw   = (const float*)d_in[19];
    const float* akv_ln_g = (const float*)d_in[20];
    const float* akv_ln_b = (const float*)d_in[21];
    const float* akv_bn_g = (const float*)d_in[22];
    const float* akv_bn_b = (const float*)d_in[23];

    float* sc = nullptr;
    cudaGetSymbolAddress((void**)&sc, g_scratch);
    float* kv     = sc;
    float* Qh     = sc + 41943040ULL;
    float* Kh     = sc + 58720256ULL;
    float* Vh     = sc + 75497472ULL;
    float* crpe   = sc + 92274688ULL;
    float* tmp    = sc + 109051904ULL;
    float* locraw = sc + 113246208ULL;
    float* obuf   = sc + 117440512ULL;
    float* mx     = sc + 138412032ULL;
    float* smv    = sc + 138416128ULL;
    float* ktv    = sc + 138420224ULL;

    // 1) kv = x @ kv_w^T   (32768 x 1280, K=640)
    sgemm_k<0><<<dim3(10, 256), 256>>>(x, 640, kv_w, kv, 1280,
                                       32768, 1280, 640, nullptr, nullptr, 0);

    // 2) aggregators: q (store loc), k (no loc), v (add loc)
    run_stream(y, 640, aq_dw3, aq_dw5, aq_dw7, aq_pw, aq_bn_g, aq_bn_b,
               Qh, tmp, locraw, obuf, true, aq_ln_g, aq_ln_b, 0);
    run_stream(kv, 1280, akv_dw3, akv_dw5, akv_dw7, akv_pw, akv_bn_g, akv_bn_b,
               Kh, tmp, locraw, obuf, false, nullptr, nullptr, 0);
    run_stream(kv + 640, 1280, akv_dw3, akv_dw5, akv_dw7, akv_pw, akv_bn_g, akv_bn_b,
               Vh, tmp, locraw, obuf, true, akv_ln_g, akv_ln_b, 1);

    // 3) attention
    softstats_k<<<64, 512>>>(Kh, mx, smv, ktv);
    ktv_k<<<dim3(8, 64), 256>>>(Kh, Vh, mx, smv, ktv);

    const long hs = 4096L * 64;           // per-head image size
    dwconv_k<3><<<dim3(1024, 16), dim3(64, 4), 64 * 9 * 4>>>(
        Vh, 8 * hs, hs, 64, crpe, 8 * hs, hs, crpe_w3, 64, 2);
    dwconv_k<5><<<dim3(1024, 24), dim3(64, 4), 64 * 25 * 4>>>(
        Vh + 2 * hs, 8 * hs, hs, 64, crpe + 2 * hs, 8 * hs, hs, crpe_w5, 64, 3);
    dwconv_k<7><<<dim3(1024, 24), dim3(64, 4), 64 * 49 * 4>>>(
        Vh + 5 * hs, 8 * hs, hs, 64, crpe + 5 * hs, 8 * hs, hs, crpe_w7, 64, 3);

    eff_k<<<dim3(64, 64), 256>>>(Qh, ktv, crpe, obuf);

    // 4) projection: out = obuf @ proj_w^T + proj_b
    sgemm_k<1><<<dim3(5, 256), 256>>>(obuf, 640, proj_w, (float*)d_out, 640,
                                      32768, 640, 640, nullptr, proj_b, 0);
}

// round 5
// speedup vs baseline: 1.3930x; 1.3930x over previous
#include <cuda_runtime.h>
#include <cuda_bf16.h>
#include <cstdint>

// ---------------------------------------------------------------------------
// CrossAtt for GB300 — round 5: all GEMMs on mma.sync bf16 (3-term fp32 split).
// Round-4 OOB fixed: THi/TLo properly sized (2,097,152 floats each).
// Shapes (fixed): B=8, H=W=64 -> N=4096, DIM=640, HEADS=8, SEG=128, CH=64.
// ---------------------------------------------------------------------------

#define RSQ_BN 0.9999950000374997f      // 1/sqrt(1+1e-5)
#define SCALE_V 0.11180339887498949f    // (640/8)^-0.5
#define LN_EPS 1e-5f

__device__ __forceinline__ float hsw(float x) {
    return x * fminf(fmaxf(x + 3.f, 0.f), 6.f) * (1.f / 6.f);
}

__device__ __forceinline__ uint32_t smem_u32(const void* p) {
    uint32_t a;
    asm("{ .reg .u64 t; cvta.to.shared.u64 t, %1; cvt.u32.u64 %0, t; }"
        : "=r"(a) : "l"(p));
    return a;
}
__device__ __forceinline__ void cp16(uint32_t s, const void* g) {
    asm volatile("cp.async.cg.shared.global [%0], [%1], 16;" :: "r"(s), "l"(g));
}
__device__ __forceinline__ void ldm_x4(uint32_t& r0, uint32_t& r1,
                                       uint32_t& r2, uint32_t& r3, uint32_t a) {
    asm volatile("ldmatrix.sync.aligned.m8n8.x4.shared.b16 {%0,%1,%2,%3}, [%4];"
        : "=r"(r0), "=r"(r1), "=r"(r2), "=r"(r3) : "r"(a));
}
__device__ __forceinline__ void mma_bf16(float* d, const uint32_t* a, const uint32_t* b) {
    asm volatile(
        "mma.sync.aligned.m16n8k16.row.col.f32.bf16.bf16.f32 "
        "{%0,%1,%2,%3},{%4,%5,%6,%7},{%8,%9},{%0,%1,%2,%3};"
        : "+f"(d[0]), "+f"(d[1]), "+f"(d[2]), "+f"(d[3])
        : "r"(a[0]), "r"(a[1]), "r"(a[2]), "r"(a[3]), "r"(b[0]), "r"(b[1]));
}

// ---------------- scratch (single bss array, no allocations) ---------------
// float offsets:
//  kv        0          (41,943,040)   (8,4096,1280)
//  Qh        41,943,040 (16,777,216)
//  Kh        58,720,256 (16,777,216)
//  Vh        75,497,472 (16,777,216)
//  crpe      92,274,688 (16,777,216)
//  PQ/PK     109,051,904 (131,072)     4x 65536 bf16 weight splits
//  locraw    113,246,208 (4,194,304)
//  obuf      117,440,512 (20,971,520)
//  mx        138,412,032 (4,096)
//  sm        138,416,128 (4,096)
//  ktv       138,420,224 (262,144)
//  Ahi       138,682,368 (10,485,760)  20,971,520 bf16
//  Alo       149,168,128 (10,485,760)
//  Whi       159,653,888 (409,600)     819,200 bf16
//  Wlo       160,063,488 (409,600)
//  THi       160,473,088 (2,097,152)   4,194,304 bf16 (32768x128)
//  TLo       162,570,240 (2,097,152)
//  end       164,667,392 floats = 658.7 MB
static __device__ __align__(256) float g_scratch[164667392ULL];

// ---------------------------------------------------------------------------
// fp32 -> bf16 hi + bf16 residual lo (elementwise, vectorized)
// ---------------------------------------------------------------------------
__global__ void cvt_k(const float* __restrict__ s, __nv_bfloat16* __restrict__ hi,
                      __nv_bfloat16* __restrict__ lo, long n)
{
    long i = ((long)blockIdx.x * blockDim.x + threadIdx.x) * 4;
    if (i >= n) return;
    float4 v = *reinterpret_cast<const float4*>(s + i);
    float a[4] = {v.x, v.y, v.z, v.w};
    __nv_bfloat16 h[4], l[4];
#pragma unroll
    for (int j = 0; j < 4; j++) {
        h[j] = __float2bfloat16(a[j]);
        l[j] = __float2bfloat16(a[j] - __bfloat162float(h[j]));
    }
    *reinterpret_cast<__nv_bfloat162*>(hi + i)     = __nv_bfloat162(h[0], h[1]);
    *reinterpret_cast<__nv_bfloat162*>(hi + i + 2) = __nv_bfloat162(h[2], h[3]);
    *reinterpret_cast<__nv_bfloat162*>(lo + i)     = __nv_bfloat162(l[0], l[1]);
    *reinterpret_cast<__nv_bfloat162*>(lo + i + 2) = __nv_bfloat162(l[2], l[3]);
}

// ---------------------------------------------------------------------------
// MMA GEMM: C[M,N] = A[M,K]*W[N,K]^T via bf16 3-term split on mma.sync.
// Block tile 128x128, 8 warps (2m x 4n), warp tile 64x32, K-chunk 16,
// 2-stage cp.async pipeline. Virtual K' = 3K (AhiWhi, AhiWlo, AloWhi).
// MODE 0: C=acc  MODE 1: C=acc+p2[n]
// MODE 2: v=hsw(acc*(p1[n]*RSQ_BN)+p2[n]) scattered to head buffer
//         C[((b*8+headBase+(n>>6))*4096 + (m&4095))*64 + (n&63)], b=m>>12
// ---------------------------------------------------------------------------
template <int MODE>
__global__ void __launch_bounds__(256) mgemm_k(
    const __nv_bfloat16* __restrict__ Ahi, const __nv_bfloat16* __restrict__ Alo,
    const __nv_bfloat16* __restrict__ Bhi, const __nv_bfloat16* __restrict__ Blo,
    float* __restrict__ C, int ldc, int K,
    const float* __restrict__ p1, const float* __restrict__ p2, int headBase)
{
    __shared__ __align__(16) char sA[2][6144];   // 128 rows x 48B (32B data+pad)
    __shared__ __align__(16) char sB[2][6144];

    const int tid = threadIdx.x;
    const int wid = tid >> 5, lane = tid & 31;
    const int warp_m = wid >> 2, warp_n = wid & 3;
    const int m0 = blockIdx.y * 128, n0 = blockIdx.x * 128;

    const int KC = K >> 4;
    const int NC = 3 * KC;

    const int lrow = tid >> 1;          // 0..127
    const int lhalf = tid & 1;          // which 16B half of the 32B row

    const uint32_t aBase[2] = {smem_u32(sA[0]), smem_u32(sA[1])};
    const uint32_t bBase[2] = {smem_u32(sB[0]), smem_u32(sB[1])};
    const uint32_t sOff = (uint32_t)(lrow * 48 + lhalf * 16);

    float acc[4][4][4] = {};

    // ldmatrix per-lane addresses (within a buffer)
    const uint32_t aLdm = (uint32_t)((warp_m * 64 + (lane & 15)) * 48 + (lane >> 4) * 16);
    const uint32_t bLdm = (uint32_t)((warp_n * 32 + (lane & 15)) * 48 + (lane >> 4) * 16);

#define ISSUE(c, buf)                                                          \
    {                                                                          \
        const int t = (c) / KC;                                                \
        const int ko = ((c) - t * KC) << 4;                                    \
        const __nv_bfloat16* As =                                              \
            (t == 2 ? Alo : Ahi) + (long)(m0 + lrow) * K + ko + lhalf * 8;     \
        const __nv_bfloat16* Bs =                                              \
            (t == 1 ? Blo : Bhi) + (long)(n0 + lrow) * K + ko + lhalf * 8;     \
        cp16(aBase[buf] + sOff, As);                                           \
        cp16(bBase[buf] + sOff, Bs);                                           \
        asm volatile("cp.async.commit_group;" ::: "memory");                   \
    }

    ISSUE(0, 0);
    int buf = 0;
    for (int c = 0; c < NC; c++) {
        if (c + 1 < NC) {
            ISSUE(c + 1, buf ^ 1);
            asm volatile("cp.async.wait_group 1;" ::: "memory");
        } else {
            asm volatile("cp.async.wait_group 0;" ::: "memory");
        }
        __syncthreads();

        uint32_t a[4][4];
#pragma unroll
        for (int mf = 0; mf < 4; mf++)
            ldm_x4(a[mf][0], a[mf][1], a[mf][2], a[mf][3],
                   aBase[buf] + aLdm + mf * 16 * 48);
        uint32_t b[4][2];
#pragma unroll
        for (int bi = 0; bi < 2; bi++) {
            uint32_t r0, r1, r2, r3;
            ldm_x4(r0, r1, r2, r3, bBase[buf] + bLdm + bi * 16 * 48);
            b[bi * 2 + 0][0] = r0; b[bi * 2 + 0][1] = r2;
            b[bi * 2 + 1][0] = r1; b[bi * 2 + 1][1] = r3;
        }
#pragma unroll
        for (int mf = 0; mf < 4; mf++)
#pragma unroll
            for (int nf = 0; nf < 4; nf++)
                mma_bf16(acc[mf][nf], a[mf], b[nf]);
        __syncthreads();
        buf ^= 1;
    }
#undef ISSUE

    // epilogue
    const int lr = lane >> 2;           // 0..7
    const int lc = (lane & 3) * 2;      // even col
#pragma unroll
    for (int mf = 0; mf < 4; mf++) {
#pragma unroll
        for (int nf = 0; nf < 4; nf++) {
            const int n = n0 + warp_n * 32 + nf * 8 + lc;
#pragma unroll
            for (int h2 = 0; h2 < 2; h2++) {
                const int m = m0 + warp_m * 64 + mf * 16 + lr + h2 * 8;
                float v0 = acc[mf][nf][2 * h2 + 0];
                float v1 = acc[mf][nf][2 * h2 + 1];
                if (MODE == 0) {
                    *reinterpret_cast<float2*>(&C[(long)m * ldc + n]) =
                        make_float2(v0, v1);
                } else if (MODE == 1) {
                    *reinterpret_cast<float2*>(&C[(long)m * ldc + n]) =
                        make_float2(v0 + p2[n], v1 + p2[n + 1]);
                } else {
                    v0 = hsw(v0 * (p1[n] * RSQ_BN) + p2[n]);
                    v1 = hsw(v1 * (p1[n + 1] * RSQ_BN) + p2[n + 1]);
                    const int bb = m >> 12, nn = m & 4095;
                    const int hh = headBase + (n >> 6), cc = n & 63;
                    *reinterpret_cast<float2*>(
                        &C[((((long)bb * 8 + hh) * 4096) + nn) * 64 + cc]) =
                        make_float2(v0, v1);
                }
            }
        }
    }
}

// ---------------------------------------------------------------------------
// seg0 branch: hardswish(BN(x)) -> head layout (heads 0,1)
// ---------------------------------------------------------------------------
__global__ void seg0_k(const float* __restrict__ in, int inRow,
                       float* __restrict__ hb,
                       const float* __restrict__ g, const float* __restrict__ bb)
{
    const int c = threadIdx.x;
    const int n = blockIdx.x * blockDim.y + threadIdx.y;
    const int b = blockIdx.y;
    float v = in[((long)b * 4096 + n) * (long)inRow + c];
    v = v * (g[c] * RSQ_BN) + bb[c];
    v = hsw(v);
    const int h = c >> 6, cc = c & 63;
    hb[(((long)b * 8 + h) * 4096 + n) * 64 + cc] = v;
}

// ---------------------------------------------------------------------------
// Depthwise conv on 64x64 image, channel-last. BF=0: fp32 out; BF=1: bf16 hi/lo.
// ---------------------------------------------------------------------------
template <int KS, int BF>
__global__ void dwconv_k(const float* __restrict__ in, long inOuter, long inInner, int inRow,
                         float* __restrict__ out,
                         __nv_bfloat16* __restrict__ ohi, __nv_bfloat16* __restrict__ olo,
                         long outOuter, long outInner,
                         const float* __restrict__ w, int C, int nh)
{
    extern __shared__ float ws[];
    const int batch = blockIdx.y;
    const int outer = batch / nh, inner = batch % nh;
    const float* ip = in + outer * inOuter + inner * inInner;
    const float* wp = w + (long)inner * C * KS * KS;

    const int nthr = blockDim.x * blockDim.y;
    const int tid = threadIdx.y * blockDim.x + threadIdx.x;
    for (int i = tid; i < C * KS * KS; i += nthr) ws[i] = wp[i];
    __syncthreads();

    const int c = threadIdx.x;
    const int pix = blockIdx.x * blockDim.y + threadIdx.y;
    const int y = pix >> 6, x = pix & 63;
    const int P = KS / 2;
    float acc = 0.f;
#pragma unroll
    for (int dy = 0; dy < KS; dy++) {
        const int yy = y + dy - P;
        if (yy < 0 || yy > 63) continue;
#pragma unroll
        for (int dx = 0; dx < KS; dx++) {
            const int xx = x + dx - P;
            if (xx < 0 || xx > 63) continue;
            acc = fmaf(ws[c * KS * KS + dy * KS + dx],
                       ip[(long)(yy * 64 + xx) * inRow + c], acc);
        }
    }
    const long oidx = outer * outOuter + inner * outInner + (long)pix * C + c;
    if (BF == 0) {
        out[oidx] = acc;
    } else {
        __nv_bfloat16 h = __float2bfloat16(acc);
        ohi[oidx] = h;
        olo[oidx] = __float2bfloat16(acc - __bfloat162float(h));
    }
}

// ---------------------------------------------------------------------------
// Softmax stats over tokens per (b,h,c); zeroes kTv accumulator.
// ---------------------------------------------------------------------------
__global__ void softstats_k(const float* __restrict__ Kh,
                            float* __restrict__ mx, float* __restrict__ sm,
                            float* __restrict__ ktv)
{
    const int bh = blockIdx.x;
    const int c  = threadIdx.x & 63;
    const int sl = threadIdx.x >> 6;
    const float* kp = Kh + (long)bh * 4096 * 64;

    float* kz = ktv + (long)bh * 4096;
    for (int i = threadIdx.x; i < 4096; i += 512) kz[i] = 0.f;

    float m = -1e30f;
    for (int j = 0; j < 512; j++) {
        const int n = sl * 512 + j;
        m = fmaxf(m, kp[(long)n * 64 + c]);
    }
    __shared__ float red[512];
    __shared__ float red2[512];
    red[threadIdx.x] = m;
    __syncthreads();
    if (sl == 0) {
        for (int s = 1; s < 8; s++) m = fmaxf(m, red[s * 64 + c]);
        red[c] = m;
    }
    __syncthreads();
    m = red[c];

    float s = 0.f;
    for (int j = 0; j < 512; j++) {
        const int n = sl * 512 + j;
        s += __expf(kp[(long)n * 64 + c] - m);
    }
    red2[threadIdx.x] = s;
    __syncthreads();
    if (sl == 0) {
        for (int ss = 1; ss < 8; ss++) s += red2[ss * 64 + c];
        mx[bh * 64 + c] = m;
        sm[bh * 64 + c] = s;
    }
}

// ---------------------------------------------------------------------------
// kTv[c1,c2] += sum_n softmax(k)[n,c1] * v[n,c2], split over 8 n-chunks.
// ---------------------------------------------------------------------------
__global__ void ktv_k(const float* __restrict__ Kh, const float* __restrict__ Vh,
                      const float* __restrict__ mx, const float* __restrict__ sm,
                      float* __restrict__ ktv)
{
    const int bh = blockIdx.y;
    const int chunk = blockIdx.x;
    const int tid = threadIdx.x;
    __shared__ float sk[4][64];
    __shared__ float sv[4][64];

    const float* kp = Kh + (long)bh * 4096 * 64;
    const float* vp = Vh + (long)bh * 4096 * 64;
    const int lc = tid & 63, lr = tid >> 6;
    const float lm = mx[bh * 64 + lc];
    const float lrs = 1.f / sm[bh * 64 + lc];

    const int i0 = (tid & 15) * 4;
    const int j0 = (tid >> 4) * 4;
    float acc[4][4] = {};

    const int nend = chunk * 512 + 512;
    for (int n0 = chunk * 512; n0 < nend; n0 += 4) {
        sk[lr][lc] = __expf(kp[(long)(n0 + lr) * 64 + lc] - lm) * lrs;
        sv[lr][lc] = vp[(long)(n0 + lr) * 64 + lc];
        __syncthreads();
#pragma unroll
        for (int r = 0; r < 4; r++) {
            float a[4], bv[4];
#pragma unroll
            for (int i = 0; i < 4; i++) a[i] = sk[r][i0 + i];
#pragma unroll
            for (int j = 0; j < 4; j++) bv[j] = sv[r][j0 + j];
#pragma unroll
            for (int i = 0; i < 4; i++)
#pragma unroll
                for (int j = 0; j < 4; j++) acc[i][j] = fmaf(a[i], bv[j], acc[i][j]);
        }
        __syncthreads();
    }
    float* kp2 = ktv + (long)bh * 4096;
#pragma unroll
    for (int i = 0; i < 4; i++)
#pragma unroll
        for (int j = 0; j < 4; j++)
            atomicAdd(&kp2[(i0 + i) * 64 + (j0 + j)], acc[i][j]);
}

// ---------------------------------------------------------------------------
// eff = q @ kTv; o = SCALE*eff + q * crpe -> obuf[b][n][h*64+c2]
// ---------------------------------------------------------------------------
__global__ void eff_k(const float* __restrict__ Qh, const float* __restrict__ ktv,
                      const float* __restrict__ crpe, float* __restrict__ obuf)
{
    const int bh = blockIdx.y;
    const int b = bh >> 3, h = bh & 7;
    const int n0 = blockIdx.x * 64;
    const int tid = threadIdx.x;

    __shared__ float skt[64][64];
    __shared__ float sq[64][65];

    const float* ktp = ktv + (long)bh * 4096;
    const float* qp  = Qh + ((long)bh * 4096 + n0) * 64;
    for (int i = tid; i < 4096; i += 256) {
        skt[i >> 6][i & 63] = ktp[i];
        sq[i >> 6][i & 63]  = qp[i];
    }
    __syncthreads();

    const int i0 = (tid & 15) * 4;
    const int j0 = (tid >> 4) * 4;
    float acc[4][4] = {};
#pragma unroll
    for (int c1 = 0; c1 < 64; c1++) {
        float a[4], bv[4];
#pragma unroll
        for (int i = 0; i < 4; i++) a[i] = sq[i0 + i][c1];
#pragma unroll
        for (int j = 0; j < 4; j++) bv[j] = skt[c1][j0 + j];
#pragma unroll
        for (int i = 0; i < 4; i++)
#pragma unroll
            for (int j = 0; j < 4; j++) acc[i][j] = fmaf(a[i], bv[j], acc[i][j]);
    }

    const float* crp = crpe + ((long)bh * 4096 + n0) * 64;
#pragma unroll
    for (int i = 0; i < 4; i++) {
        const int n = n0 + i0 + i;
#pragma unroll
        for (int j = 0; j < 4; j++) {
            const int c2 = j0 + j;
            const float q = sq[i0 + i][c2];
            const float cr = q * crp[(long)(i0 + i) * 64 + c2];
            obuf[((long)b * 4096 + n) * 640 + h * 64 + c2] = SCALE_V * acc[i][j] + cr;
        }
    }
}

// ---------------------------------------------------------------------------
// LayerNorm(128) + hardswish, write (or add) into obuf channels [512,640).
// ---------------------------------------------------------------------------
__global__ void ln_k(const float* __restrict__ in,
                     const float* __restrict__ g, const float* __restrict__ bb,
                     float* __restrict__ obuf, int addMode)
{
    const int row  = blockIdx.x * 8 + (threadIdx.x >> 5);
    const int lane = threadIdx.x & 31;
    const float* ip = in + (long)row * 128;
    float4 v = reinterpret_cast<const float4*>(ip)[lane];
    float s  = v.x + v.y + v.z + v.w;
    float sq = v.x * v.x + v.y * v.y + v.z * v.z + v.w * v.w;
#pragma unroll
    for (int o = 16; o > 0; o >>= 1) {
        s  += __shfl_xor_sync(0xffffffffu, s, o);
        sq += __shfl_xor_sync(0xffffffffu, sq, o);
    }
    const float m = s * (1.f / 128.f);
    const float var = sq * (1.f / 128.f) - m * m;
    const float r = rsqrtf(var + LN_EPS);
    const int c0 = lane * 4;
    float vals[4] = {v.x, v.y, v.z, v.w};
    float* op = obuf + (long)row * 640 + 512 + c0;
    float out[4];
#pragma unroll
    for (int i = 0; i < 4; i++) {
        float vv = (vals[i] - m) * r * g[c0 + i] + bb[c0 + i];
        vv = hsw(vv);
        out[i] = addMode ? (op[i] + vv) : vv;
    }
    *reinterpret_cast<float4*>(op) = make_float4(out[0], out[1], out[2], out[3]);
}

// ---------------------------------------------------------------------------
// One aggregator stream: seg0 + 3 conv branches (+ optional local branch).
// ---------------------------------------------------------------------------
static void run_stream(const float* base, int rowStride,
                       const float* dw3, const float* dw5, const float* dw7,
                       const __nv_bfloat16* pwh, const __nv_bfloat16* pwl,
                       const float* bng, const float* bnb,
                       float* headbuf, __nv_bfloat16* THi, __nv_bfloat16* TLo,
                       float* locraw, float* obuf,
                       bool doLoc, const float* lng, const float* lnb, int locAdd)
{
    const long inOuter = 4096L * rowStride;
    const long outO = 4096L * 128;

    seg0_k<<<dim3(2048, 8), dim3(128, 2)>>>(base, rowStride, headbuf, bng, bnb);

    dwconv_k<3, 1><<<dim3(2048, 8), dim3(128, 2), 128 * 9 * 4>>>(
        base + 128, inOuter, 0, rowStride, nullptr, THi, TLo, outO, 0,
        dw3 + 128 * 9, 128, 1);
    mgemm_k<2><<<dim3(1, 256), 256>>>(THi, TLo, pwh + 16384, pwl + 16384,
                                      headbuf, 0, 128, bng + 128, bnb + 128, 2);
    dwconv_k<5, 1><<<dim3(2048, 8), dim3(128, 2), 128 * 25 * 4>>>(
        base + 256, inOuter, 0, rowStride, nullptr, THi, TLo, outO, 0,
        dw5, 128, 1);
    mgemm_k<2><<<dim3(1, 256), 256>>>(THi, TLo, pwh + 2 * 16384, pwl + 2 * 16384,
                                      headbuf, 0, 128, bng + 256, bnb + 256, 4);
    dwconv_k<7, 1><<<dim3(2048, 8), dim3(128, 2), 128 * 49 * 4>>>(
        base + 384, inOuter, 0, rowStride, nullptr, THi, TLo, outO, 0,
        dw7, 128, 1);
    mgemm_k<2><<<dim3(1, 256), 256>>>(THi, TLo, pwh + 3 * 16384, pwl + 3 * 16384,
                                      headbuf, 0, 128, bng + 384, bnb + 384, 6);

    if (doLoc) {
        dwconv_k<3, 1><<<dim3(2048, 8), dim3(128, 2), 128 * 9 * 4>>>(
            base + 512, inOuter, 0, rowStride, nullptr, THi, TLo, outO, 0,
            dw3, 128, 1);
        mgemm_k<0><<<dim3(1, 256), 256>>>(THi, TLo, pwh, pwl, locraw, 128, 128,
                                          nullptr, nullptr, 0);
        ln_k<<<4096, 256>>>(locraw, lng, lnb, obuf, locAdd);
    }
}

// ---------------------------------------------------------------------------
extern "C" void kernel_launch(void* const* d_in, const int* in_sizes, int n_in,
                              void* d_out, int out_size)
{
    (void)in_sizes; (void)n_in; (void)out_size;
    const float* x        = (const float*)d_in[0];
    const float* y        = (const float*)d_in[1];
    const float* kv_w     = (const float*)d_in[2];
    const float* proj_w   = (const float*)d_in[3];
    const float* proj_b   = (const float*)d_in[4];
    const float* crpe_w3  = (const float*)d_in[5];
    const float* crpe_w5  = (const float*)d_in[6];
    const float* crpe_w7  = (const float*)d_in[7];
    const float* aq_dw3   = (const float*)d_in[8];
    const float* aq_dw5   = (const float*)d_in[9];
    const float* aq_dw7   = (const float*)d_in[10];
    const float* aq_pw    = (const float*)d_in[11];
    const float* aq_ln_g  = (const float*)d_in[12];
    const float* aq_ln_b  = (const float*)d_in[13];
    const float* aq_bn_g  = (const float*)d_in[14];
    const float* aq_bn_b  = (const float*)d_in[15];
    const float* akv_dw3  = (const float*)d_in[16];
    const float* akv_dw5  = (const float*)d_in[17];
    const float* akv_dw7  = (const float*)d_in[18];
    const float* akv_pw   = (const float*)d_in[19];
    const float* akv_ln_g = (const float*)d_in[20];
    const float* akv_ln_b = (const float*)d_in[21];
    const float* akv_bn_g = (const float*)d_in[22];
    const float* akv_bn_b = (const float*)d_in[23];

    float* sc = nullptr;
    cudaGetSymbolAddress((void**)&sc, g_scratch);
    float* kv     = sc;
    float* Qh     = sc + 41943040ULL;
    float* Kh     = sc + 58720256ULL;
    float* Vh     = sc + 75497472ULL;
    float* crpe   = sc + 92274688ULL;
    __nv_bfloat16* PQh = (__nv_bfloat16*)(sc + 109051904ULL);  // 65536 bf16
    __nv_bfloat16* PQl = (__nv_bfloat16*)(sc + 109084672ULL);
    __nv_bfloat16* PKh = (__nv_bfloat16*)(sc + 109117440ULL);
    __nv_bfloat16* PKl = (__nv_bfloat16*)(sc + 109150208ULL);
    float* locraw = sc + 113246208ULL;
    float* obuf   = sc + 117440512ULL;
    float* mx     = sc + 138412032ULL;
    float* smv    = sc + 138416128ULL;
    float* ktv    = sc + 138420224ULL;
    __nv_bfloat16* Ahi = (__nv_bfloat16*)(sc + 138682368ULL);
    __nv_bfloat16* Alo = (__nv_bfloat16*)(sc + 149168128ULL);
    __nv_bfloat16* Whi = (__nv_bfloat16*)(sc + 159653888ULL);
    __nv_bfloat16* Wlo = (__nv_bfloat16*)(sc + 160063488ULL);
    __nv_bfloat16* THi = (__nv_bfloat16*)(sc + 160473088ULL);  // 4,194,304 bf16
    __nv_bfloat16* TLo = (__nv_bfloat16*)(sc + 162570240ULL);  // 4,194,304 bf16

    // 1) kv = x @ kv_w^T on tensor cores (bf16 split)
    cvt_k<<<20480, 256>>>(x, Ahi, Alo, 20971520L);            // 8*4096*640
    cvt_k<<<800, 256>>>(kv_w, Whi, Wlo, 819200L);             // 1280*640
    mgemm_k<0><<<dim3(10, 256), 256>>>(Ahi, Alo, Whi, Wlo, kv, 1280, 640,
                                       nullptr, nullptr, 0);

    // pointwise-conv weight splits
    cvt_k<<<64, 256>>>(aq_pw, PQh, PQl, 65536L);
    cvt_k<<<64, 256>>>(akv_pw, PKh, PKl, 65536L);

    // 2) aggregators: q (store loc), k (no loc), v (add loc)
    run_stream(y, 640, aq_dw3, aq_dw5, aq_dw7, PQh, PQl, aq_bn_g, aq_bn_b,
               Qh, THi, TLo, locraw, obuf, true, aq_ln_g, aq_ln_b, 0);
    run_stream(kv, 1280, akv_dw3, akv_dw5, akv_dw7, PKh, PKl, akv_bn_g, akv_bn_b,
               Kh, THi, TLo, locraw, obuf, false, nullptr, nullptr, 0);
    run_stream(kv + 640, 1280, akv_dw3, akv_dw5, akv_dw7, PKh, PKl, akv_bn_g, akv_bn_b,
               Vh, THi, TLo, locraw, obuf, true, akv_ln_g, akv_ln_b, 1);

    // 3) attention
    softstats_k<<<64, 512>>>(Kh, mx, smv, ktv);
    ktv_k<<<dim3(8, 64), 256>>>(Kh, Vh, mx, smv, ktv);

    const long hs = 4096L * 64;
    dwconv_k<3, 0><<<dim3(1024, 16), dim3(64, 4), 64 * 9 * 4>>>(
        Vh, 8 * hs, hs, 64, crpe, nullptr, nullptr, 8 * hs, hs, crpe_w3, 64, 2);
    dwconv_k<5, 0><<<dim3(1024, 24), dim3(64, 4), 64 * 25 * 4>>>(
        Vh + 2 * hs, 8 * hs, hs, 64, crpe + 2 * hs, nullptr, nullptr, 8 * hs, hs,
        crpe_w5, 64, 3);
    dwconv_k<7, 0><<<dim3(1024, 24), dim3(64, 4), 64 * 49 * 4>>>(
        Vh + 5 * hs, 8 * hs, hs, 64, crpe + 5 * hs, nullptr, nullptr, 8 * hs, hs,
        crpe_w7, 64, 3);

    eff_k<<<dim3(64, 64), 256>>>(Qh, ktv, crpe, obuf);

    // 4) projection: out = obuf @ proj_w^T + proj_b (tensor cores)
    cvt_k<<<20480, 256>>>(obuf, Ahi, Alo, 20971520L);
    cvt_k<<<400, 256>>>(proj_w, Whi, Wlo, 409600L);
    mgemm_k<1><<<dim3(5, 256), 256>>>(Ahi, Alo, Whi, Wlo, (float*)d_out, 640, 640,
                                      nullptr, proj_b, 0);
}

// round 6
// speedup vs baseline: 1.5357x; 1.1024x over previous
#include <cuda_runtime.h>
#include <cuda_bf16.h>
#include <cstdint>

// ---------------------------------------------------------------------------
// CrossAtt for GB300 — round 6:
//  * mgemm v2: BK=32, 3-stage cp.async pipeline, 2 CTAs/SM
//  * dwconv: 8-pixel blocks for L1 tap reuse
//  * eff/ln emit bf16 hi/lo directly (no obuf cvt pass)
// Shapes: B=8, H=W=64 -> N=4096, DIM=640, HEADS=8, SEG=128, CH=64.
// ---------------------------------------------------------------------------

#define RSQ_BN 0.9999950000374997f      // 1/sqrt(1+1e-5)
#define SCALE_V 0.11180339887498949f    // (640/8)^-0.5
#define LN_EPS 1e-5f

__device__ __forceinline__ float hsw(float x) {
    return x * fminf(fmaxf(x + 3.f, 0.f), 6.f) * (1.f / 6.f);
}

__device__ __forceinline__ uint32_t smem_u32(const void* p) {
    uint32_t a;
    asm("{ .reg .u64 t; cvta.to.shared.u64 t, %1; cvt.u32.u64 %0, t; }"
        : "=r"(a) : "l"(p));
    return a;
}
__device__ __forceinline__ void cp16(uint32_t s, const void* g) {
    asm volatile("cp.async.cg.shared.global [%0], [%1], 16;" :: "r"(s), "l"(g));
}
__device__ __forceinline__ void ldm_x4(uint32_t& r0, uint32_t& r1,
                                       uint32_t& r2, uint32_t& r3, uint32_t a) {
    asm volatile("ldmatrix.sync.aligned.m8n8.x4.shared.b16 {%0,%1,%2,%3}, [%4];"
        : "=r"(r0), "=r"(r1), "=r"(r2), "=r"(r3) : "r"(a));
}
__device__ __forceinline__ void mma_bf16(float* d, const uint32_t* a, const uint32_t* b) {
    asm volatile(
        "mma.sync.aligned.m16n8k16.row.col.f32.bf16.bf16.f32 "
        "{%0,%1,%2,%3},{%4,%5,%6,%7},{%8,%9},{%0,%1,%2,%3};"
        : "+f"(d[0]), "+f"(d[1]), "+f"(d[2]), "+f"(d[3])
        : "r"(a[0]), "r"(a[1]), "r"(a[2]), "r"(a[3]), "r"(b[0]), "r"(b[1]));
}
__device__ __forceinline__ void split_bf16(float v, __nv_bfloat16& h, __nv_bfloat16& l) {
    h = __float2bfloat16(v);
    l = __float2bfloat16(v - __bfloat162float(h));
}

// ---------------- scratch (single bss array, no allocations) ---------------
// float offsets:
//  kv        0          (41,943,040)
//  Qh        41,943,040 (16,777,216)
//  Kh        58,720,256 (16,777,216)
//  Vh        75,497,472 (16,777,216)
//  crpe      92,274,688 (16,777,216)
//  PQ/PK     109,051,904 (131,072)
//  locraw    113,246,208 (4,194,304)
//  locsum    117,440,512 (4,194,304)   (re-uses old obuf region)
//  mx        138,412,032 (4,096)
//  sm        138,416,128 (4,096)
//  ktv       138,420,224 (262,144)
//  Ahi       138,682,368 (10,485,760)  20,971,520 bf16 (32768x640)
//  Alo       149,168,128 (10,485,760)
//  Whi       159,653,888 (409,600)
//  Wlo       160,063,488 (409,600)
//  THi       160,473,088 (2,097,152)   4,194,304 bf16 (32768x128)
//  TLo       162,570,240 (2,097,152)
//  end       164,667,392 floats
static __device__ __align__(256) float g_scratch[164667392ULL];

// ---------------------------------------------------------------------------
// fp32 -> bf16 hi + lo residual
// ---------------------------------------------------------------------------
__global__ void cvt_k(const float* __restrict__ s, __nv_bfloat16* __restrict__ hi,
                      __nv_bfloat16* __restrict__ lo, long n)
{
    long i = ((long)blockIdx.x * blockDim.x + threadIdx.x) * 4;
    if (i >= n) return;
    float4 v = *reinterpret_cast<const float4*>(s + i);
    float a[4] = {v.x, v.y, v.z, v.w};
    __nv_bfloat16 h[4], l[4];
#pragma unroll
    for (int j = 0; j < 4; j++) split_bf16(a[j], h[j], l[j]);
    *reinterpret_cast<__nv_bfloat162*>(hi + i)     = __nv_bfloat162(h[0], h[1]);
    *reinterpret_cast<__nv_bfloat162*>(hi + i + 2) = __nv_bfloat162(h[2], h[3]);
    *reinterpret_cast<__nv_bfloat162*>(lo + i)     = __nv_bfloat162(l[0], l[1]);
    *reinterpret_cast<__nv_bfloat162*>(lo + i + 2) = __nv_bfloat162(l[2], l[3]);
}

// ---------------------------------------------------------------------------
// MMA GEMM v2: C[M,N] = A[M,K]*W[N,K]^T via bf16 3-term split.
// Block tile 128x128, 8 warps (2m x 4n), BK=32 per stage, 3-stage cp.async
// pipeline, one __syncthreads per stage, 2 CTAs/SM.
// Requires K % 32 == 0 and (K/16) even. Virtual K' = 3K.
// smem: 6 tiles x 10240B = 61440B dynamic.
// ---------------------------------------------------------------------------
#define MG_SMEM 61440

template <int MODE>
__global__ void __launch_bounds__(256, 2) mgemm_k(
    const __nv_bfloat16* __restrict__ Ahi, const __nv_bfloat16* __restrict__ Alo,
    const __nv_bfloat16* __restrict__ Bhi, const __nv_bfloat16* __restrict__ Blo,
    float* __restrict__ C, int ldc, int K,
    const float* __restrict__ p1, const float* __restrict__ p2, int headBase)
{
    extern __shared__ __align__(16) char smem[];
    const uint32_t sbase = smem_u32(smem);

    const int tid = threadIdx.x;
    const int wid = tid >> 5, lane = tid & 31;
    const int warp_m = wid >> 2, warp_n = wid & 3;
    const int m0 = blockIdx.y * 128, n0 = blockIdx.x * 128;

    const int KC = K >> 4;           // k16 steps per term
    const int SC = (3 * KC) >> 1;    // 32-wide stages

    // cp.async chunk mapping: 512 chunks of 16B per tile (128 rows x 4 chunks)
    const int r0c = tid >> 2,        c40 = tid & 3;          // chunk tid
    const int r1c = (tid + 256) >> 2, c41 = (tid + 256) & 3; // chunk tid+256

    float acc[4][4][4] = {};

    const uint32_t aLdm = (uint32_t)((warp_m * 64 + (lane & 15)) * 80 + (lane >> 4) * 16);
    const uint32_t bLdm = (uint32_t)((warp_n * 32 + (lane & 15)) * 80 + (lane >> 4) * 16);

#define A_OFF(st) ((uint32_t)(st) * 10240u)
#define B_OFF(st) (30720u + (uint32_t)(st) * 10240u)

#define ISSUE(s, st)                                                           \
    {                                                                          \
        const int t = (2 * (s)) / KC;                                          \
        const int ko = ((2 * (s)) % KC) << 4;                                  \
        const __nv_bfloat16* Ab = (t == 2 ? Alo : Ahi) + (long)m0 * K + ko;    \
        const __nv_bfloat16* Bb = (t == 1 ? Blo : Bhi) + (long)n0 * K + ko;    \
        cp16(sbase + A_OFF(st) + r0c * 80 + c40 * 16, Ab + (long)r0c * K + c40 * 8); \
        cp16(sbase + B_OFF(st) + r0c * 80 + c40 * 16, Bb + (long)r0c * K + c40 * 8); \
        cp16(sbase + A_OFF(st) + r1c * 80 + c41 * 16, Ab + (long)r1c * K + c41 * 8); \
        cp16(sbase + B_OFF(st) + r1c * 80 + c41 * 16, Bb + (long)r1c * K + c41 * 8); \
        asm volatile("cp.async.commit_group;" ::: "memory");                   \
    }

    ISSUE(0, 0);
    ISSUE(1, 1);

    for (int s = 0; s < SC; s++) {
        const int st = s % 3;
        if (s + 1 < SC) {
            asm volatile("cp.async.wait_group 1;" ::: "memory");
        } else {
            asm volatile("cp.async.wait_group 0;" ::: "memory");
        }
        __syncthreads();

#pragma unroll
        for (int ks = 0; ks < 2; ks++) {
            uint32_t a[4][4];
#pragma unroll
            for (int mf = 0; mf < 4; mf++)
                ldm_x4(a[mf][0], a[mf][1], a[mf][2], a[mf][3],
                       sbase + A_OFF(st) + aLdm + mf * 16 * 80 + ks * 32);
            uint32_t b[4][2];
#pragma unroll
            for (int bi = 0; bi < 2; bi++) {
                uint32_t q0, q1, q2, q3;
                ldm_x4(q0, q1, q2, q3,
                       sbase + B_OFF(st) + bLdm + bi * 16 * 80 + ks * 32);
                b[bi * 2 + 0][0] = q0; b[bi * 2 + 0][1] = q2;
                b[bi * 2 + 1][0] = q1; b[bi * 2 + 1][1] = q3;
            }
#pragma unroll
            for (int mf = 0; mf < 4; mf++)
#pragma unroll
                for (int nf = 0; nf < 4; nf++)
                    mma_bf16(acc[mf][nf], a[mf], b[nf]);
        }
        if (s + 2 < SC) ISSUE(s + 2, (s + 2) % 3);
    }
#undef ISSUE
#undef A_OFF
#undef B_OFF

    // epilogue
    const int lr = lane >> 2;
    const int lc = (lane & 3) * 2;
#pragma unroll
    for (int mf = 0; mf < 4; mf++) {
#pragma unroll
        for (int nf = 0; nf < 4; nf++) {
            const int n = n0 + warp_n * 32 + nf * 8 + lc;
#pragma unroll
            for (int h2 = 0; h2 < 2; h2++) {
                const int m = m0 + warp_m * 64 + mf * 16 + lr + h2 * 8;
                float v0 = acc[mf][nf][2 * h2 + 0];
                float v1 = acc[mf][nf][2 * h2 + 1];
                if (MODE == 0) {
                    *reinterpret_cast<float2*>(&C[(long)m * ldc + n]) =
                        make_float2(v0, v1);
                } else if (MODE == 1) {
                    *reinterpret_cast<float2*>(&C[(long)m * ldc + n]) =
                        make_float2(v0 + p2[n], v1 + p2[n + 1]);
                } else {
                    v0 = hsw(v0 * (p1[n] * RSQ_BN) + p2[n]);
                    v1 = hsw(v1 * (p1[n + 1] * RSQ_BN) + p2[n + 1]);
                    const int bb = m >> 12, nn = m & 4095;
                    const int hh = headBase + (n >> 6), cc = n & 63;
                    *reinterpret_cast<float2*>(
                        &C[((((long)bb * 8 + hh) * 4096) + nn) * 64 + cc]) =
                        make_float2(v0, v1);
                }
            }
        }
    }
}

// ---------------------------------------------------------------------------
// seg0 branch: hardswish(BN(x)) -> head layout (heads 0,1)
// ---------------------------------------------------------------------------
__global__ void seg0_k(const float* __restrict__ in, int inRow,
                       float* __restrict__ hb,
                       const float* __restrict__ g, const float* __restrict__ bb)
{
    const int c = threadIdx.x;
    const int n = blockIdx.x * blockDim.y + threadIdx.y;
    const int b = blockIdx.y;
    float v = in[((long)b * 4096 + n) * (long)inRow + c];
    v = v * (g[c] * RSQ_BN) + bb[c];
    v = hsw(v);
    const int h = c >> 6, cc = c & 63;
    hb[(((long)b * 8 + h) * 4096 + n) * 64 + cc] = v;
}

// ---------------------------------------------------------------------------
// Depthwise conv on 64x64 image, channel-last. BF=0 fp32 out; BF=1 bf16 hi/lo.
// blockDim (C, 8): 8 consecutive pixels share tap rows via L1.
// ---------------------------------------------------------------------------
template <int KS, int BF>
__global__ void dwconv_k(const float* __restrict__ in, long inOuter, long inInner, int inRow,
                         float* __restrict__ out,
                         __nv_bfloat16* __restrict__ ohi, __nv_bfloat16* __restrict__ olo,
                         long outOuter, long outInner,
                         const float* __restrict__ w, int C, int nh)
{
    extern __shared__ float ws[];
    const int batch = blockIdx.y;
    const int outer = batch / nh, inner = batch % nh;
    const float* ip = in + outer * inOuter + inner * inInner;
    const float* wp = w + (long)inner * C * KS * KS;

    const int nthr = blockDim.x * blockDim.y;
    const int tid = threadIdx.y * blockDim.x + threadIdx.x;
    for (int i = tid; i < C * KS * KS; i += nthr) ws[i] = wp[i];
    __syncthreads();

    const int c = threadIdx.x;
    const int pix = blockIdx.x * blockDim.y + threadIdx.y;
    const int y = pix >> 6, x = pix & 63;
    const int P = KS / 2;
    float acc = 0.f;
#pragma unroll
    for (int dy = 0; dy < KS; dy++) {
        const int yy = y + dy - P;
        if (yy < 0 || yy > 63) continue;
#pragma unroll
        for (int dx = 0; dx < KS; dx++) {
            const int xx = x + dx - P;
            if (xx < 0 || xx > 63) continue;
            acc = fmaf(ws[c * KS * KS + dy * KS + dx],
                       ip[(long)(yy * 64 + xx) * inRow + c], acc);
        }
    }
    const long oidx = outer * outOuter + inner * outInner + (long)pix * C + c;
    if (BF == 0) {
        out[oidx] = acc;
    } else {
        __nv_bfloat16 h, l;
        split_bf16(acc, h, l);
        ohi[oidx] = h;
        olo[oidx] = l;
    }
}

// ---------------------------------------------------------------------------
// Softmax stats over tokens per (b,h,c); zeroes kTv accumulator.
// ---------------------------------------------------------------------------
__global__ void softstats_k(const float* __restrict__ Kh,
                            float* __restrict__ mx, float* __restrict__ sm,
                            float* __restrict__ ktv)
{
    const int bh = blockIdx.x;
    const int c  = threadIdx.x & 63;
    const int sl = threadIdx.x >> 6;
    const float* kp = Kh + (long)bh * 4096 * 64;

    float* kz = ktv + (long)bh * 4096;
    for (int i = threadIdx.x; i < 4096; i += 512) kz[i] = 0.f;

    float m = -1e30f;
    for (int j = 0; j < 512; j++) {
        const int n = sl * 512 + j;
        m = fmaxf(m, kp[(long)n * 64 + c]);
    }
    __shared__ float red[512];
    __shared__ float red2[512];
    red[threadIdx.x] = m;
    __syncthreads();
    if (sl == 0) {
        for (int s = 1; s < 8; s++) m = fmaxf(m, red[s * 64 + c]);
        red[c] = m;
    }
    __syncthreads();
    m = red[c];

    float s = 0.f;
    for (int j = 0; j < 512; j++) {
        const int n = sl * 512 + j;
        s += __expf(kp[(long)n * 64 + c] - m);
    }
    red2[threadIdx.x] = s;
    __syncthreads();
    if (sl == 0) {
        for (int ss = 1; ss < 8; ss++) s += red2[ss * 64 + c];
        mx[bh * 64 + c] = m;
        sm[bh * 64 + c] = s;
    }
}

// ---------------------------------------------------------------------------
// kTv[c1,c2] += sum_n softmax(k)[n,c1] * v[n,c2], split over 8 n-chunks.
// ---------------------------------------------------------------------------
__global__ void ktv_k(const float* __restrict__ Kh, const float* __restrict__ Vh,
                      const float* __restrict__ mx, const float* __restrict__ sm,
                      float* __restrict__ ktv)
{
    const int bh = blockIdx.y;
    const int chunk = blockIdx.x;
    const int tid = threadIdx.x;
    __shared__ float sk[4][64];
    __shared__ float sv[4][64];

    const float* kp = Kh + (long)bh * 4096 * 64;
    const float* vp = Vh + (long)bh * 4096 * 64;
    const int lc = tid & 63, lr = tid >> 6;
    const float lm = mx[bh * 64 + lc];
    const float lrs = 1.f / sm[bh * 64 + lc];

    const int i0 = (tid & 15) * 4;
    const int j0 = (tid >> 4) * 4;
    float acc[4][4] = {};

    const int nend = chunk * 512 + 512;
    for (int n0 = chunk * 512; n0 < nend; n0 += 4) {
        sk[lr][lc] = __expf(kp[(long)(n0 + lr) * 64 + lc] - lm) * lrs;
        sv[lr][lc] = vp[(long)(n0 + lr) * 64 + lc];
        __syncthreads();
#pragma unroll
        for (int r = 0; r < 4; r++) {
            float a[4], bv[4];
#pragma unroll
            for (int i = 0; i < 4; i++) a[i] = sk[r][i0 + i];
#pragma unroll
            for (int j = 0; j < 4; j++) bv[j] = sv[r][j0 + j];
#pragma unroll
            for (int i = 0; i < 4; i++)
#pragma unroll
                for (int j = 0; j < 4; j++) acc[i][j] = fmaf(a[i], bv[j], acc[i][j]);
        }
        __syncthreads();
    }
    float* kp2 = ktv + (long)bh * 4096;
#pragma unroll
    for (int i = 0; i < 4; i++)
#pragma unroll
        for (int j = 0; j < 4; j++)
            atomicAdd(&kp2[(i0 + i) * 64 + (j0 + j)], acc[i][j]);
}

// ---------------------------------------------------------------------------
// eff = q @ kTv; o = SCALE*eff + q*crpe -> bf16 hi/lo into proj-A buffers
// at row (b*4096+n), col h*64+c2 of the (32768,640) layout.
// ---------------------------------------------------------------------------
__global__ void eff_k(const float* __restrict__ Qh, const float* __restrict__ ktv,
                      const float* __restrict__ crpe,
                      __nv_bfloat16* __restrict__ ohi, __nv_bfloat16* __restrict__ olo)
{
    const int bh = blockIdx.y;
    const int b = bh >> 3, h = bh & 7;
    const int n0 = blockIdx.x * 64;
    const int tid = threadIdx.x;

    __shared__ float skt[64][64];
    __shared__ float sq[64][65];

    const float* ktp = ktv + (long)bh * 4096;
    const float* qp  = Qh + ((long)bh * 4096 + n0) * 64;
    for (int i = tid; i < 4096; i += 256) {
        skt[i >> 6][i & 63] = ktp[i];
        sq[i >> 6][i & 63]  = qp[i];
    }
    __syncthreads();

    const int i0 = (tid & 15) * 4;
    const int j0 = (tid >> 4) * 4;
    float acc[4][4] = {};
#pragma unroll
    for (int c1 = 0; c1 < 64; c1++) {
        float a[4], bv[4];
#pragma unroll
        for (int i = 0; i < 4; i++) a[i] = sq[i0 + i][c1];
#pragma unroll
        for (int j = 0; j < 4; j++) bv[j] = skt[c1][j0 + j];
#pragma unroll
        for (int i = 0; i < 4; i++)
#pragma unroll
            for (int j = 0; j < 4; j++) acc[i][j] = fmaf(a[i], bv[j], acc[i][j]);
    }

    const float* crp = crpe + ((long)bh * 4096 + n0) * 64;
#pragma unroll
    for (int i = 0; i < 4; i++) {
        const int n = n0 + i0 + i;
        const long rbase = ((long)b * 4096 + n) * 640 + h * 64;
#pragma unroll
        for (int j = 0; j < 4; j++) {
            const int c2 = j0 + j;
            const float q = sq[i0 + i][c2];
            const float cr = q * crp[(long)(i0 + i) * 64 + c2];
            const float v = SCALE_V * acc[i][j] + cr;
            __nv_bfloat16 hh, ll;
            split_bf16(v, hh, ll);
            ohi[rbase + c2] = hh;
            olo[rbase + c2] = ll;
        }
    }
}

// ---------------------------------------------------------------------------
// LayerNorm(128) + hardswish.
//  mode 0: write fp32 into locsum (32768x128)
//  mode 1: val += locsum; split bf16 into proj-A cols [512,640)
// ---------------------------------------------------------------------------
__global__ void ln_k(const float* __restrict__ in,
                     const float* __restrict__ g, const float* __restrict__ bb,
                     float* __restrict__ locsum,
                     __nv_bfloat16* __restrict__ ohi, __nv_bfloat16* __restrict__ olo,
                     int addMode)
{
    const int row  = blockIdx.x * 8 + (threadIdx.x >> 5);
    const int lane = threadIdx.x & 31;
    const float* ip = in + (long)row * 128;
    float4 v = reinterpret_cast<const float4*>(ip)[lane];
    float s  = v.x + v.y + v.z + v.w;
    float sq = v.x * v.x + v.y * v.y + v.z * v.z + v.w * v.w;
#pragma unroll
    for (int o = 16; o > 0; o >>= 1) {
        s  += __shfl_xor_sync(0xffffffffu, s, o);
        sq += __shfl_xor_sync(0xffffffffu, sq, o);
    }
    const float m = s * (1.f / 128.f);
    const float var = sq * (1.f / 128.f) - m * m;
    const float r = rsqrtf(var + LN_EPS);
    const int c0 = lane * 4;
    float vals[4] = {v.x, v.y, v.z, v.w};
    if (!addMode) {
        float out[4];
#pragma unroll
        for (int i = 0; i < 4; i++)
            out[i] = hsw((vals[i] - m) * r * g[c0 + i] + bb[c0 + i]);
        *reinterpret_cast<float4*>(&locsum[(long)row * 128 + c0]) =
            make_float4(out[0], out[1], out[2], out[3]);
    } else {
        const float4 prev = *reinterpret_cast<const float4*>(&locsum[(long)row * 128 + c0]);
        const float pv[4] = {prev.x, prev.y, prev.z, prev.w};
        __nv_bfloat16 h[4], l[4];
#pragma unroll
        for (int i = 0; i < 4; i++) {
            float vv = hsw((vals[i] - m) * r * g[c0 + i] + bb[c0 + i]) + pv[i];
            split_bf16(vv, h[i], l[i]);
        }
        const long ob = (long)row * 640 + 512 + c0;
        *reinterpret_cast<__nv_bfloat162*>(&ohi[ob])     = __nv_bfloat162(h[0], h[1]);
        *reinterpret_cast<__nv_bfloat162*>(&ohi[ob + 2]) = __nv_bfloat162(h[2], h[3]);
        *reinterpret_cast<__nv_bfloat162*>(&olo[ob])     = __nv_bfloat162(l[0], l[1]);
        *reinterpret_cast<__nv_bfloat162*>(&olo[ob + 2]) = __nv_bfloat162(l[2], l[3]);
    }
}

// ---------------------------------------------------------------------------
// One aggregator stream: seg0 + 3 conv branches (+ optional local branch).
// ---------------------------------------------------------------------------
static void run_stream(const float* base, int rowStride,
                       const float* dw3, const float* dw5, const float* dw7,
                       const __nv_bfloat16* pwh, const __nv_bfloat16* pwl,
                       const float* bng, const float* bnb,
                       float* headbuf, __nv_bfloat16* THi, __nv_bfloat16* TLo,
                       float* locraw, float* locsum,
                       __nv_bfloat16* ohi, __nv_bfloat16* olo,
                       bool doLoc, const float* lng, const float* lnb, int locAdd)
{
    const long inOuter = 4096L * rowStride;
    const long outO = 4096L * 128;
    const dim3 dwGrid(512, 8), dwBlk(128, 8);

    seg0_k<<<dim3(2048, 8), dim3(128, 2)>>>(base, rowStride, headbuf, bng, bnb);

    dwconv_k<3, 1><<<dwGrid, dwBlk, 128 * 9 * 4>>>(
        base + 128, inOuter, 0, rowStride, nullptr, THi, TLo, outO, 0,
        dw3 + 128 * 9, 128, 1);
    mgemm_k<2><<<dim3(1, 256), 256, MG_SMEM>>>(THi, TLo, pwh + 16384, pwl + 16384,
                                               headbuf, 0, 128, bng + 128, bnb + 128, 2);
    dwconv_k<5, 1><<<dwGrid, dwBlk, 128 * 25 * 4>>>(
        base + 256, inOuter, 0, rowStride, nullptr, THi, TLo, outO, 0,
        dw5, 128, 1);
    mgemm_k<2><<<dim3(1, 256), 256, MG_SMEM>>>(THi, TLo, pwh + 2 * 16384, pwl + 2 * 16384,
                                               headbuf, 0, 128, bng + 256, bnb + 256, 4);
    dwconv_k<7, 1><<<dwGrid, dwBlk, 128 * 49 * 4>>>(
        base + 384, inOuter, 0, rowStride, nullptr, THi, TLo, outO, 0,
        dw7, 128, 1);
    mgemm_k<2><<<dim3(1, 256), 256, MG_SMEM>>>(THi, TLo, pwh + 3 * 16384, pwl + 3 * 16384,
                                               headbuf, 0, 128, bng + 384, bnb + 384, 6);

    if (doLoc) {
        dwconv_k<3, 1><<<dwGrid, dwBlk, 128 * 9 * 4>>>(
            base + 512, inOuter, 0, rowStride, nullptr, THi, TLo, outO, 0,
            dw3, 128, 1);
        mgemm_k<0><<<dim3(1, 256), 256, MG_SMEM>>>(THi, TLo, pwh, pwl, locraw, 128, 128,
                                                   nullptr, nullptr, 0);
        ln_k<<<4096, 256>>>(locraw, lng, lnb, locsum, ohi, olo, locAdd);
    }
}

// ---------------------------------------------------------------------------
extern "C" void kernel_launch(void* const* d_in, const int* in_sizes, int n_in,
                              void* d_out, int out_size)
{
    (void)in_sizes; (void)n_in; (void)out_size;
    const float* x        = (const float*)d_in[0];
    const float* y        = (const float*)d_in[1];
    const float* kv_w     = (const float*)d_in[2];
    const float* proj_w   = (const float*)d_in[3];
    const float* proj_b   = (const float*)d_in[4];
    const float* crpe_w3  = (const float*)d_in[5];
    const float* crpe_w5  = (const float*)d_in[6];
    const float* crpe_w7  = (const float*)d_in[7];
    const float* aq_dw3   = (const float*)d_in[8];
    const float* aq_dw5   = (const float*)d_in[9];
    const float* aq_dw7   = (const float*)d_in[10];
    const float* aq_pw    = (const float*)d_in[11];
    const float* aq_ln_g  = (const float*)d_in[12];
    const float* aq_ln_b  = (const float*)d_in[13];
    const float* aq_bn_g  = (const float*)d_in[14];
    const float* aq_bn_b  = (const float*)d_in[15];
    const float* akv_dw3  = (const float*)d_in[16];
    const float* akv_dw5  = (const float*)d_in[17];
    const float* akv_dw7  = (const float*)d_in[18];
    const float* akv_pw   = (const float*)d_in[19];
    const float* akv_ln_g = (const float*)d_in[20];
    const float* akv_ln_b = (const float*)d_in[21];
    const float* akv_bn_g = (const float*)d_in[22];
    const float* akv_bn_b = (const float*)d_in[23];

    float* sc = nullptr;
    cudaGetSymbolAddress((void**)&sc, g_scratch);
    float* kv     = sc;
    float* Qh     = sc + 41943040ULL;
    float* Kh     = sc + 58720256ULL;
    float* Vh     = sc + 75497472ULL;
    float* crpe   = sc + 92274688ULL;
    __nv_bfloat16* PQh = (__nv_bfloat16*)(sc + 109051904ULL);
    __nv_bfloat16* PQl = (__nv_bfloat16*)(sc + 109084672ULL);
    __nv_bfloat16* PKh = (__nv_bfloat16*)(sc + 109117440ULL);
    __nv_bfloat16* PKl = (__nv_bfloat16*)(sc + 109150208ULL);
    float* locraw = sc + 113246208ULL;
    float* locsum = sc + 117440512ULL;
    float* mx     = sc + 138412032ULL;
    float* smv    = sc + 138416128ULL;
    float* ktv    = sc + 138420224ULL;
    __nv_bfloat16* Ahi = (__nv_bfloat16*)(sc + 138682368ULL);
    __nv_bfloat16* Alo = (__nv_bfloat16*)(sc + 149168128ULL);
    __nv_bfloat16* Whi = (__nv_bfloat16*)(sc + 159653888ULL);
    __nv_bfloat16* Wlo = (__nv_bfloat16*)(sc + 160063488ULL);
    __nv_bfloat16* THi = (__nv_bfloat16*)(sc + 160473088ULL);
    __nv_bfloat16* TLo = (__nv_bfloat16*)(sc + 162570240ULL);

    cudaFuncSetAttribute(mgemm_k<0>, cudaFuncAttributeMaxDynamicSharedMemorySize, MG_SMEM);
    cudaFuncSetAttribute(mgemm_k<1>, cudaFuncAttributeMaxDynamicSharedMemorySize, MG_SMEM);
    cudaFuncSetAttribute(mgemm_k<2>, cudaFuncAttributeMaxDynamicSharedMemorySize, MG_SMEM);

    // 1) kv = x @ kv_w^T (tensor cores, bf16 split)
    cvt_k<<<20480, 256>>>(x, Ahi, Alo, 20971520L);
    cvt_k<<<800, 256>>>(kv_w, Whi, Wlo, 819200L);
    mgemm_k<0><<<dim3(10, 256), 256, MG_SMEM>>>(Ahi, Alo, Whi, Wlo, kv, 1280, 640,
                                                nullptr, nullptr, 0);

    // pointwise-conv weight splits
    cvt_k<<<64, 256>>>(aq_pw, PQh, PQl, 65536L);
    cvt_k<<<64, 256>>>(akv_pw, PKh, PKl, 65536L);

    // 2) aggregators: q (loc -> locsum), k (no loc), v (loc add -> proj-A)
    run_stream(y, 640, aq_dw3, aq_dw5, aq_dw7, PQh, PQl, aq_bn_g, aq_bn_b,
               Qh, THi, TLo, locraw, locsum, Ahi, Alo, true, aq_ln_g, aq_ln_b, 0);
    run_stream(kv, 1280, akv_dw3, akv_dw5, akv_dw7, PKh, PKl, akv_bn_g, akv_bn_b,
               Kh, THi, TLo, locraw, locsum, Ahi, Alo, false, nullptr, nullptr, 0);
    run_stream(kv + 640, 1280, akv_dw3, akv_dw5, akv_dw7, PKh, PKl, akv_bn_g, akv_bn_b,
               Vh, THi, TLo, locraw, locsum, Ahi, Alo, true, akv_ln_g, akv_ln_b, 1);

    // 3) attention
    softstats_k<<<64, 512>>>(Kh, mx, smv, ktv);
    ktv_k<<<dim3(8, 64), 256>>>(Kh, Vh, mx, smv, ktv);

    const long hs = 4096L * 64;
    dwconv_k<3, 0><<<dim3(512, 16), dim3(64, 8), 64 * 9 * 4>>>(
        Vh, 8 * hs, hs, 64, crpe, nullptr, nullptr, 8 * hs, hs, crpe_w3, 64, 2);
    dwconv_k<5, 0><<<dim3(512, 24), dim3(64, 8), 64 * 25 * 4>>>(
        Vh + 2 * hs, 8 * hs, hs, 64, crpe + 2 * hs, nullptr, nullptr, 8 * hs, hs,
        crpe_w5, 64, 3);
    dwconv_k<7, 0><<<dim3(512, 24), dim3(64, 8), 64 * 49 * 4>>>(
        Vh + 5 * hs, 8 * hs, hs, 64, crpe + 5 * hs, nullptr, nullptr, 8 * hs, hs,
        crpe_w7, 64, 3);

    // eff writes bf16 hi/lo directly into proj-A cols [0,512)
    eff_k<<<dim3(64, 64), 256>>>(Qh, ktv, crpe, Ahi, Alo);

    // 4) projection: out = projA @ proj_w^T + proj_b (tensor cores)
    cvt_k<<<400, 256>>>(proj_w, Whi, Wlo, 409600L);
    mgemm_k<1><<<dim3(5, 256), 256, MG_SMEM>>>(Ahi, Alo, Whi, Wlo, (float*)d_out, 640, 640,
                                               nullptr, proj_b, 0);
}

// round 7
// speedup vs baseline: 1.5419x; 1.0041x over previous
#include <cuda_runtime.h>
#include <cuda_bf16.h>
#include <cstdint>

// ---------------------------------------------------------------------------
// CrossAtt for GB300 — round 7: mgemm v3 — hi/lo tiles loaded once per k16
// stage, 3 MMA terms share one accumulator. 3-stage cp.async pipeline,
// 2 CTAs/SM. kv mgemm moved to launch slot 6 for ncu capture.
// Shapes: B=8, H=W=64 -> N=4096, DIM=640, HEADS=8, SEG=128, CH=64.
// ---------------------------------------------------------------------------

#define RSQ_BN 0.9999950000374997f      // 1/sqrt(1+1e-5)
#define SCALE_V 0.11180339887498949f    // (640/8)^-0.5
#define LN_EPS 1e-5f

__device__ __forceinline__ float hsw(float x) {
    return x * fminf(fmaxf(x + 3.f, 0.f), 6.f) * (1.f / 6.f);
}

__device__ __forceinline__ uint32_t smem_u32(const void* p) {
    uint32_t a;
    asm("{ .reg .u64 t; cvta.to.shared.u64 t, %1; cvt.u32.u64 %0, t; }"
        : "=r"(a) : "l"(p));
    return a;
}
__device__ __forceinline__ void cp16(uint32_t s, const void* g) {
    asm volatile("cp.async.cg.shared.global [%0], [%1], 16;" :: "r"(s), "l"(g));
}
__device__ __forceinline__ void ldm_x4(uint32_t& r0, uint32_t& r1,
                                       uint32_t& r2, uint32_t& r3, uint32_t a) {
    asm volatile("ldmatrix.sync.aligned.m8n8.x4.shared.b16 {%0,%1,%2,%3}, [%4];"
        : "=r"(r0), "=r"(r1), "=r"(r2), "=r"(r3) : "r"(a));
}
__device__ __forceinline__ void mma_bf16(float* d, const uint32_t* a, const uint32_t* b) {
    asm volatile(
        "mma.sync.aligned.m16n8k16.row.col.f32.bf16.bf16.f32 "
        "{%0,%1,%2,%3},{%4,%5,%6,%7},{%8,%9},{%0,%1,%2,%3};"
        : "+f"(d[0]), "+f"(d[1]), "+f"(d[2]), "+f"(d[3])
        : "r"(a[0]), "r"(a[1]), "r"(a[2]), "r"(a[3]), "r"(b[0]), "r"(b[1]));
}
__device__ __forceinline__ void split_bf16(float v, __nv_bfloat16& h, __nv_bfloat16& l) {
    h = __float2bfloat16(v);
    l = __float2bfloat16(v - __bfloat162float(h));
}

// ---------------- scratch (single bss array, no allocations) ---------------
static __device__ __align__(256) float g_scratch[164667392ULL];

// ---------------------------------------------------------------------------
// fp32 -> bf16 hi + lo residual
// ---------------------------------------------------------------------------
__global__ void cvt_k(const float* __restrict__ s, __nv_bfloat16* __restrict__ hi,
                      __nv_bfloat16* __restrict__ lo, long n)
{
    long i = ((long)blockIdx.x * blockDim.x + threadIdx.x) * 4;
    if (i >= n) return;
    float4 v = *reinterpret_cast<const float4*>(s + i);
    float a[4] = {v.x, v.y, v.z, v.w};
    __nv_bfloat16 h[4], l[4];
#pragma unroll
    for (int j = 0; j < 4; j++) split_bf16(a[j], h[j], l[j]);
    *reinterpret_cast<__nv_bfloat162*>(hi + i)     = __nv_bfloat162(h[0], h[1]);
    *reinterpret_cast<__nv_bfloat162*>(hi + i + 2) = __nv_bfloat162(h[2], h[3]);
    *reinterpret_cast<__nv_bfloat162*>(lo + i)     = __nv_bfloat162(l[0], l[1]);
    *reinterpret_cast<__nv_bfloat162*>(lo + i + 2) = __nv_bfloat162(l[2], l[3]);
}

// ---------------------------------------------------------------------------
// MMA GEMM v3: C[M,N] = A[M,K]*W[N,K]^T, bf16 split with shared hi/lo loads.
// Block 128x128, 8 warps (2m x 4n), stage = k16 with 4 tiles (Ahi,Alo,Bhi,Blo),
// 3-stage cp.async pipeline, 3 MMA terms per fragment into one accumulator.
// K % 16 == 0. smem: 3 stages x 24576B = 73728B dynamic.
// MODE 0: C=acc  MODE 1: C=acc+p2[n]
// MODE 2: v=hsw(acc*(p1[n]*RSQ_BN)+p2[n]) scattered to head buffer
// ---------------------------------------------------------------------------
#define MG_SMEM 73728

template <int MODE>
__global__ void __launch_bounds__(256, 2) mgemm_k(
    const __nv_bfloat16* __restrict__ Ahi, const __nv_bfloat16* __restrict__ Alo,
    const __nv_bfloat16* __restrict__ Bhi, const __nv_bfloat16* __restrict__ Blo,
    float* __restrict__ C, int ldc, int K,
    const float* __restrict__ p1, const float* __restrict__ p2, int headBase)
{
    extern __shared__ __align__(16) char smem[];
    const uint32_t sbase = smem_u32(smem);

    const int tid = threadIdx.x;
    const int wid = tid >> 5, lane = tid & 31;
    const int warp_m = wid >> 2, warp_n = wid & 3;
    const int m0 = blockIdx.y * 128, n0 = blockIdx.x * 128;

    const int SC = K >> 4;               // k16 stages

    const int row = tid >> 1, half = tid & 1;     // cp.async mapping (128x2)
    const uint32_t soff = (uint32_t)(row * 48 + half * 16);
    const long aRow = (long)(m0 + row) * K + half * 8;
    const long bRow = (long)(n0 + row) * K + half * 8;

    float acc[4][4][4] = {};

    const uint32_t aLdm = (uint32_t)((warp_m * 64 + (lane & 15)) * 48 + (lane >> 4) * 16);
    const uint32_t bLdm = (uint32_t)((warp_n * 32 + (lane & 15)) * 48 + (lane >> 4) * 16);

#define ST_BASE(st) (sbase + (uint32_t)(st) * 24576u)

#define ISSUE(s, st)                                                           \
    {                                                                          \
        const int ko = (s) << 4;                                               \
        const uint32_t sb = ST_BASE(st);                                       \
        cp16(sb + soff,          Ahi + aRow + ko);                             \
        cp16(sb + 6144u + soff,  Alo + aRow + ko);                             \
        cp16(sb + 12288u + soff, Bhi + bRow + ko);                             \
        cp16(sb + 18432u + soff, Blo + bRow + ko);                             \
        asm volatile("cp.async.commit_group;" ::: "memory");                   \
    }

    ISSUE(0, 0);
    ISSUE(1, 1);

    for (int s = 0; s < SC; s++) {
        const int st = s % 3;
        if (s + 1 < SC) {
            asm volatile("cp.async.wait_group 1;" ::: "memory");
        } else {
            asm volatile("cp.async.wait_group 0;" ::: "memory");
        }
        __syncthreads();

        const uint32_t sb = ST_BASE(st);

        // B fragments (hi + lo), kept live across both A loads
        uint32_t bh[4][2], bl[4][2];
#pragma unroll
        for (int bi = 0; bi < 2; bi++) {
            uint32_t q0, q1, q2, q3;
            ldm_x4(q0, q1, q2, q3, sb + 12288u + bLdm + bi * 768u);
            bh[bi * 2 + 0][0] = q0; bh[bi * 2 + 0][1] = q2;
            bh[bi * 2 + 1][0] = q1; bh[bi * 2 + 1][1] = q3;
            ldm_x4(q0, q1, q2, q3, sb + 18432u + bLdm + bi * 768u);
            bl[bi * 2 + 0][0] = q0; bl[bi * 2 + 0][1] = q2;
            bl[bi * 2 + 1][0] = q1; bl[bi * 2 + 1][1] = q3;
        }

        // term 1+2: Ahi * (Bhi + Blo)
#pragma unroll
        for (int mf = 0; mf < 4; mf++) {
            uint32_t a[4];
            ldm_x4(a[0], a[1], a[2], a[3], sb + aLdm + mf * 768u);
#pragma unroll
            for (int nf = 0; nf < 4; nf++) {
                mma_bf16(acc[mf][nf], a, bh[nf]);
                mma_bf16(acc[mf][nf], a, bl[nf]);
            }
        }
        // term 3: Alo * Bhi
#pragma unroll
        for (int mf = 0; mf < 4; mf++) {
            uint32_t a[4];
            ldm_x4(a[0], a[1], a[2], a[3], sb + 6144u + aLdm + mf * 768u);
#pragma unroll
            for (int nf = 0; nf < 4; nf++)
                mma_bf16(acc[mf][nf], a, bh[nf]);
        }

        if (s + 2 < SC) ISSUE(s + 2, (s + 2) % 3);
    }
#undef ISSUE
#undef ST_BASE

    // epilogue
    const int lr = lane >> 2;
    const int lc = (lane & 3) * 2;
#pragma unroll
    for (int mf = 0; mf < 4; mf++) {
#pragma unroll
        for (int nf = 0; nf < 4; nf++) {
            const int n = n0 + warp_n * 32 + nf * 8 + lc;
#pragma unroll
            for (int h2 = 0; h2 < 2; h2++) {
                const int m = m0 + warp_m * 64 + mf * 16 + lr + h2 * 8;
                float v0 = acc[mf][nf][2 * h2 + 0];
                float v1 = acc[mf][nf][2 * h2 + 1];
                if (MODE == 0) {
                    *reinterpret_cast<float2*>(&C[(long)m * ldc + n]) =
                        make_float2(v0, v1);
                } else if (MODE == 1) {
                    *reinterpret_cast<float2*>(&C[(long)m * ldc + n]) =
                        make_float2(v0 + p2[n], v1 + p2[n + 1]);
                } else {
                    v0 = hsw(v0 * (p1[n] * RSQ_BN) + p2[n]);
                    v1 = hsw(v1 * (p1[n + 1] * RSQ_BN) + p2[n + 1]);
                    const int bb = m >> 12, nn = m & 4095;
                    const int hh = headBase + (n >> 6), cc = n & 63;
                    *reinterpret_cast<float2*>(
                        &C[((((long)bb * 8 + hh) * 4096) + nn) * 64 + cc]) =
                        make_float2(v0, v1);
                }
            }
        }
    }
}

// ---------------------------------------------------------------------------
// seg0 branch: hardswish(BN(x)) -> head layout (heads 0,1)
// ---------------------------------------------------------------------------
__global__ void seg0_k(const float* __restrict__ in, int inRow,
                       float* __restrict__ hb,
                       const float* __restrict__ g, const float* __restrict__ bb)
{
    const int c = threadIdx.x;
    const int n = blockIdx.x * blockDim.y + threadIdx.y;
    const int b = blockIdx.y;
    float v = in[((long)b * 4096 + n) * (long)inRow + c];
    v = v * (g[c] * RSQ_BN) + bb[c];
    v = hsw(v);
    const int h = c >> 6, cc = c & 63;
    hb[(((long)b * 8 + h) * 4096 + n) * 64 + cc] = v;
}

// ---------------------------------------------------------------------------
// Depthwise conv on 64x64 image, channel-last. BF=0 fp32 out; BF=1 bf16 hi/lo.
// ---------------------------------------------------------------------------
template <int KS, int BF>
__global__ void dwconv_k(const float* __restrict__ in, long inOuter, long inInner, int inRow,
                         float* __restrict__ out,
                         __nv_bfloat16* __restrict__ ohi, __nv_bfloat16* __restrict__ olo,
                         long outOuter, long outInner,
                         const float* __restrict__ w, int C, int nh)
{
    extern __shared__ float ws[];
    const int batch = blockIdx.y;
    const int outer = batch / nh, inner = batch % nh;
    const float* ip = in + outer * inOuter + inner * inInner;
    const float* wp = w + (long)inner * C * KS * KS;

    const int nthr = blockDim.x * blockDim.y;
    const int tid = threadIdx.y * blockDim.x + threadIdx.x;
    for (int i = tid; i < C * KS * KS; i += nthr) ws[i] = wp[i];
    __syncthreads();

    const int c = threadIdx.x;
    const int pix = blockIdx.x * blockDim.y + threadIdx.y;
    const int y = pix >> 6, x = pix & 63;
    const int P = KS / 2;
    float acc = 0.f;
#pragma unroll
    for (int dy = 0; dy < KS; dy++) {
        const int yy = y + dy - P;
        if (yy < 0 || yy > 63) continue;
#pragma unroll
        for (int dx = 0; dx < KS; dx++) {
            const int xx = x + dx - P;
            if (xx < 0 || xx > 63) continue;
            acc = fmaf(ws[c * KS * KS + dy * KS + dx],
                       ip[(long)(yy * 64 + xx) * inRow + c], acc);
        }
    }
    const long oidx = outer * outOuter + inner * outInner + (long)pix * C + c;
    if (BF == 0) {
        out[oidx] = acc;
    } else {
        __nv_bfloat16 h, l;
        split_bf16(acc, h, l);
        ohi[oidx] = h;
        olo[oidx] = l;
    }
}

// ---------------------------------------------------------------------------
// Softmax stats over tokens per (b,h,c); zeroes kTv accumulator.
// ---------------------------------------------------------------------------
__global__ void softstats_k(const float* __restrict__ Kh,
                            float* __restrict__ mx, float* __restrict__ sm,
                            float* __restrict__ ktv)
{
    const int bh = blockIdx.x;
    const int c  = threadIdx.x & 63;
    const int sl = threadIdx.x >> 6;
    const float* kp = Kh + (long)bh * 4096 * 64;

    float* kz = ktv + (long)bh * 4096;
    for (int i = threadIdx.x; i < 4096; i += 512) kz[i] = 0.f;

    float m = -1e30f;
    for (int j = 0; j < 512; j++) {
        const int n = sl * 512 + j;
        m = fmaxf(m, kp[(long)n * 64 + c]);
    }
    __shared__ float red[512];
    __shared__ float red2[512];
    red[threadIdx.x] = m;
    __syncthreads();
    if (sl == 0) {
        for (int s = 1; s < 8; s++) m = fmaxf(m, red[s * 64 + c]);
        red[c] = m;
    }
    __syncthreads();
    m = red[c];

    float s = 0.f;
    for (int j = 0; j < 512; j++) {
        const int n = sl * 512 + j;
        s += __expf(kp[(long)n * 64 + c] - m);
    }
    red2[threadIdx.x] = s;
    __syncthreads();
    if (sl == 0) {
        for (int ss = 1; ss < 8; ss++) s += red2[ss * 64 + c];
        mx[bh * 64 + c] = m;
        sm[bh * 64 + c] = s;
    }
}

// ---------------------------------------------------------------------------
// kTv[c1,c2] += sum_n softmax(k)[n,c1] * v[n,c2], split over 8 n-chunks.
// ---------------------------------------------------------------------------
__global__ void ktv_k(const float* __restrict__ Kh, const float* __restrict__ Vh,
                      const float* __restrict__ mx, const float* __restrict__ sm,
                      float* __restrict__ ktv)
{
    const int bh = blockIdx.y;
    const int chunk = blockIdx.x;
    const int tid = threadIdx.x;
    __shared__ float sk[4][64];
    __shared__ float sv[4][64];

    const float* kp = Kh + (long)bh * 4096 * 64;
    const float* vp = Vh + (long)bh * 4096 * 64;
    const int lc = tid & 63, lr = tid >> 6;
    const float lm = mx[bh * 64 + lc];
    const float lrs = 1.f / sm[bh * 64 + lc];

    const int i0 = (tid & 15) * 4;
    const int j0 = (tid >> 4) * 4;
    float acc[4][4] = {};

    const int nend = chunk * 512 + 512;
    for (int n0 = chunk * 512; n0 < nend; n0 += 4) {
        sk[lr][lc] = __expf(kp[(long)(n0 + lr) * 64 + lc] - lm) * lrs;
        sv[lr][lc] = vp[(long)(n0 + lr) * 64 + lc];
        __syncthreads();
#pragma unroll
        for (int r = 0; r < 4; r++) {
            float a[4], bv[4];
#pragma unroll
            for (int i = 0; i < 4; i++) a[i] = sk[r][i0 + i];
#pragma unroll
            for (int j = 0; j < 4; j++) bv[j] = sv[r][j0 + j];
#pragma unroll
            for (int i = 0; i < 4; i++)
#pragma unroll
                for (int j = 0; j < 4; j++) acc[i][j] = fmaf(a[i], bv[j], acc[i][j]);
        }
        __syncthreads();
    }
    float* kp2 = ktv + (long)bh * 4096;
#pragma unroll
    for (int i = 0; i < 4; i++)
#pragma unroll
        for (int j = 0; j < 4; j++)
            atomicAdd(&kp2[(i0 + i) * 64 + (j0 + j)], acc[i][j]);
}

// ---------------------------------------------------------------------------
// eff = q @ kTv; o = SCALE*eff + q*crpe -> bf16 hi/lo into proj-A buffers.
// ---------------------------------------------------------------------------
__global__ void eff_k(const float* __restrict__ Qh, const float* __restrict__ ktv,
                      const float* __restrict__ crpe,
                      __nv_bfloat16* __restrict__ ohi, __nv_bfloat16* __restrict__ olo)
{
    const int bh = blockIdx.y;
    const int b = bh >> 3, h = bh & 7;
    const int n0 = blockIdx.x * 64;
    const int tid = threadIdx.x;

    __shared__ float skt[64][64];
    __shared__ float sq[64][65];

    const float* ktp = ktv + (long)bh * 4096;
    const float* qp  = Qh + ((long)bh * 4096 + n0) * 64;
    for (int i = tid; i < 4096; i += 256) {
        skt[i >> 6][i & 63] = ktp[i];
        sq[i >> 6][i & 63]  = qp[i];
    }
    __syncthreads();

    const int i0 = (tid & 15) * 4;
    const int j0 = (tid >> 4) * 4;
    float acc[4][4] = {};
#pragma unroll
    for (int c1 = 0; c1 < 64; c1++) {
        float a[4], bv[4];
#pragma unroll
        for (int i = 0; i < 4; i++) a[i] = sq[i0 + i][c1];
#pragma unroll
        for (int j = 0; j < 4; j++) bv[j] = skt[c1][j0 + j];
#pragma unroll
        for (int i = 0; i < 4; i++)
#pragma unroll
            for (int j = 0; j < 4; j++) acc[i][j] = fmaf(a[i], bv[j], acc[i][j]);
    }

    const float* crp = crpe + ((long)bh * 4096 + n0) * 64;
#pragma unroll
    for (int i = 0; i < 4; i++) {
        const int n = n0 + i0 + i;
        const long rbase = ((long)b * 4096 + n) * 640 + h * 64;
#pragma unroll
        for (int j = 0; j < 4; j++) {
            const int c2 = j0 + j;
            const float q = sq[i0 + i][c2];
            const float cr = q * crp[(long)(i0 + i) * 64 + c2];
            const float v = SCALE_V * acc[i][j] + cr;
            __nv_bfloat16 hh, ll;
            split_bf16(v, hh, ll);
            ohi[rbase + c2] = hh;
            olo[rbase + c2] = ll;
        }
    }
}

// ---------------------------------------------------------------------------
// LayerNorm(128) + hardswish.
//  mode 0: write fp32 into locsum; mode 1: add locsum, bf16 -> proj-A [512,640)
// ---------------------------------------------------------------------------
__global__ void ln_k(const float* __restrict__ in,
                     const float* __restrict__ g, const float* __restrict__ bb,
                     float* __restrict__ locsum,
                     __nv_bfloat16* __restrict__ ohi, __nv_bfloat16* __restrict__ olo,
                     int addMode)
{
    const int row  = blockIdx.x * 8 + (threadIdx.x >> 5);
    const int lane = threadIdx.x & 31;
    const float* ip = in + (long)row * 128;
    float4 v = reinterpret_cast<const float4*>(ip)[lane];
    float s  = v.x + v.y + v.z + v.w;
    float sq = v.x * v.x + v.y * v.y + v.z * v.z + v.w * v.w;
#pragma unroll
    for (int o = 16; o > 0; o >>= 1) {
        s  += __shfl_xor_sync(0xffffffffu, s, o);
        sq += __shfl_xor_sync(0xffffffffu, sq, o);
    }
    const float m = s * (1.f / 128.f);
    const float var = sq * (1.f / 128.f) - m * m;
    const float r = rsqrtf(var + LN_EPS);
    const int c0 = lane * 4;
    float vals[4] = {v.x, v.y, v.z, v.w};
    if (!addMode) {
        float out[4];
#pragma unroll
        for (int i = 0; i < 4; i++)
            out[i] = hsw((vals[i] - m) * r * g[c0 + i] + bb[c0 + i]);
        *reinterpret_cast<float4*>(&locsum[(long)row * 128 + c0]) =
            make_float4(out[0], out[1], out[2], out[3]);
    } else {
        const float4 prev = *reinterpret_cast<const float4*>(&locsum[(long)row * 128 + c0]);
        const float pv[4] = {prev.x, prev.y, prev.z, prev.w};
        __nv_bfloat16 h[4], l[4];
#pragma unroll
        for (int i = 0; i < 4; i++) {
            float vv = hsw((vals[i] - m) * r * g[c0 + i] + bb[c0 + i]) + pv[i];
            split_bf16(vv, h[i], l[i]);
        }
        const long ob = (long)row * 640 + 512 + c0;
        *reinterpret_cast<__nv_bfloat162*>(&ohi[ob])     = __nv_bfloat162(h[0], h[1]);
        *reinterpret_cast<__nv_bfloat162*>(&ohi[ob + 2]) = __nv_bfloat162(h[2], h[3]);
        *reinterpret_cast<__nv_bfloat162*>(&olo[ob])     = __nv_bfloat162(l[0], l[1]);
        *reinterpret_cast<__nv_bfloat162*>(&olo[ob + 2]) = __nv_bfloat162(l[2], l[3]);
    }
}

// ---------------------------------------------------------------------------
// One aggregator stream: seg0 + 3 conv branches (+ optional local branch).
// ---------------------------------------------------------------------------
static void run_stream(const float* base, int rowStride,
                       const float* dw3, const float* dw5, const float* dw7,
                       const __nv_bfloat16* pwh, const __nv_bfloat16* pwl,
                       const float* bng, const float* bnb,
                       float* headbuf, __nv_bfloat16* THi, __nv_bfloat16* TLo,
                       float* locraw, float* locsum,
                       __nv_bfloat16* ohi, __nv_bfloat16* olo,
                       bool doLoc, const float* lng, const float* lnb, int locAdd)
{
    const long inOuter = 4096L * rowStride;
    const long outO = 4096L * 128;
    const dim3 dwGrid(512, 8), dwBlk(128, 8);

    seg0_k<<<dim3(2048, 8), dim3(128, 2)>>>(base, rowStride, headbuf, bng, bnb);

    dwconv_k<3, 1><<<dwGrid, dwBlk, 128 * 9 * 4>>>(
        base + 128, inOuter, 0, rowStride, nullptr, THi, TLo, outO, 0,
        dw3 + 128 * 9, 128, 1);
    mgemm_k<2><<<dim3(1, 256), 256, MG_SMEM>>>(THi, TLo, pwh + 16384, pwl + 16384,
                                               headbuf, 0, 128, bng + 128, bnb + 128, 2);
    dwconv_k<5, 1><<<dwGrid, dwBlk, 128 * 25 * 4>>>(
        base + 256, inOuter, 0, rowStride, nullptr, THi, TLo, outO, 0,
        dw5, 128, 1);
    mgemm_k<2><<<dim3(1, 256), 256, MG_SMEM>>>(THi, TLo, pwh + 2 * 16384, pwl + 2 * 16384,
                                               headbuf, 0, 128, bng + 256, bnb + 256, 4);
    dwconv_k<7, 1><<<dwGrid, dwBlk, 128 * 49 * 4>>>(
        base + 384, inOuter, 0, rowStride, nullptr, THi, TLo, outO, 0,
        dw7, 128, 1);
    mgemm_k<2><<<dim3(1, 256), 256, MG_SMEM>>>(THi, TLo, pwh + 3 * 16384, pwl + 3 * 16384,
                                               headbuf, 0, 128, bng + 384, bnb + 384, 6);

    if (doLoc) {
        dwconv_k<3, 1><<<dwGrid, dwBlk, 128 * 9 * 4>>>(
            base + 512, inOuter, 0, rowStride, nullptr, THi, TLo, outO, 0,
            dw3, 128, 1);
        mgemm_k<0><<<dim3(1, 256), 256, MG_SMEM>>>(THi, TLo, pwh, pwl, locraw, 128, 128,
                                                   nullptr, nullptr, 0);
        ln_k<<<4096, 256>>>(locraw, lng, lnb, locsum, ohi, olo, locAdd);
    }
}

// ---------------------------------------------------------------------------
extern "C" void kernel_launch(void* const* d_in, const int* in_sizes, int n_in,
                              void* d_out, int out_size)
{
    (void)in_sizes; (void)n_in; (void)out_size;
    const float* x        = (const float*)d_in[0];
    const float* y        = (const float*)d_in[1];
    const float* kv_w     = (const float*)d_in[2];
    const float* proj_w   = (const float*)d_in[3];
    const float* proj_b   = (const float*)d_in[4];
    const float* crpe_w3  = (const float*)d_in[5];
    const float* crpe_w5  = (const float*)d_in[6];
    const float* crpe_w7  = (const float*)d_in[7];
    const float* aq_dw3   = (const float*)d_in[8];
    const float* aq_dw5   = (const float*)d_in[9];
    const float* aq_dw7   = (const float*)d_in[10];
    const float* aq_pw    = (const float*)d_in[11];
    const float* aq_ln_g  = (const float*)d_in[12];
    const float* aq_ln_b  = (const float*)d_in[13];
    const float* aq_bn_g  = (const float*)d_in[14];
    const float* aq_bn_b  = (const float*)d_in[15];
    const float* akv_dw3  = (const float*)d_in[16];
    const float* akv_dw5  = (const float*)d_in[17];
    const float* akv_dw7  = (const float*)d_in[18];
    const float* akv_pw   = (const float*)d_in[19];
    const float* akv_ln_g = (const float*)d_in[20];
    const float* akv_ln_b = (const float*)d_in[21];
    const float* akv_bn_g = (const float*)d_in[22];
    const float* akv_bn_b = (const float*)d_in[23];

    float* sc = nullptr;
    cudaGetSymbolAddress((void**)&sc, g_scratch);
    float* kv     = sc;
    float* Qh     = sc + 41943040ULL;
    float* Kh     = sc + 58720256ULL;
    float* Vh     = sc + 75497472ULL;
    float* crpe   = sc + 92274688ULL;
    __nv_bfloat16* PQh = (__nv_bfloat16*)(sc + 109051904ULL);
    __nv_bfloat16* PQl = (__nv_bfloat16*)(sc + 109084672ULL);
    __nv_bfloat16* PKh = (__nv_bfloat16*)(sc + 109117440ULL);
    __nv_bfloat16* PKl = (__nv_bfloat16*)(sc + 109150208ULL);
    float* locraw = sc + 113246208ULL;
    float* locsum = sc + 117440512ULL;
    float* mx     = sc + 138412032ULL;
    float* smv    = sc + 138416128ULL;
    float* ktv    = sc + 138420224ULL;
    __nv_bfloat16* Ahi = (__nv_bfloat16*)(sc + 138682368ULL);
    __nv_bfloat16* Alo = (__nv_bfloat16*)(sc + 149168128ULL);
    __nv_bfloat16* Whi = (__nv_bfloat16*)(sc + 159653888ULL);
    __nv_bfloat16* Wlo = (__nv_bfloat16*)(sc + 160063488ULL);
    __nv_bfloat16* THi = (__nv_bfloat16*)(sc + 160473088ULL);
    __nv_bfloat16* TLo = (__nv_bfloat16*)(sc + 162570240ULL);
    // proj weight split gets its own slot (after PK splits, region is free)
    __nv_bfloat16* PWh = (__nv_bfloat16*)(sc + 109182976ULL);   // 409,600 bf16
    __nv_bfloat16* PWl = (__nv_bfloat16*)(sc + 109387776ULL);

    cudaFuncSetAttribute(mgemm_k<0>, cudaFuncAttributeMaxDynamicSharedMemorySize, MG_SMEM);
    cudaFuncSetAttribute(mgemm_k<1>, cudaFuncAttributeMaxDynamicSharedMemorySize, MG_SMEM);
    cudaFuncSetAttribute(mgemm_k<2>, cudaFuncAttributeMaxDynamicSharedMemorySize, MG_SMEM);

    // launches 1-5: all small cvt work, so launch 6 (profiled) = kv mgemm
    cvt_k<<<20480, 256>>>(x, Ahi, Alo, 20971520L);            // 1
    cvt_k<<<800, 256>>>(kv_w, Whi, Wlo, 819200L);             // 2
    cvt_k<<<64, 256>>>(aq_pw, PQh, PQl, 65536L);              // 3
    cvt_k<<<64, 256>>>(akv_pw, PKh, PKl, 65536L);             // 4
    cvt_k<<<400, 256>>>(proj_w, PWh, PWl, 409600L);           // 5
    // 6: kv = x @ kv_w^T  (PROFILED)
    mgemm_k<0><<<dim3(10, 256), 256, MG_SMEM>>>(Ahi, Alo, Whi, Wlo, kv, 1280, 640,
                                                nullptr, nullptr, 0);

    // aggregators: q (loc -> locsum), k (no loc), v (loc add -> proj-A)
    run_stream(y, 640, aq_dw3, aq_dw5, aq_dw7, PQh, PQl, aq_bn_g, aq_bn_b,
               Qh, THi, TLo, locraw, locsum, Ahi, Alo, true, aq_ln_g, aq_ln_b, 0);
    run_stream(kv, 1280, akv_dw3, akv_dw5, akv_dw7, PKh, PKl, akv_bn_g, akv_bn_b,
               Kh, THi, TLo, locraw, locsum, Ahi, Alo, false, nullptr, nullptr, 0);
    run_stream(kv + 640, 1280, akv_dw3, akv_dw5, akv_dw7, PKh, PKl, akv_bn_g, akv_bn_b,
               Vh, THi, TLo, locraw, locsum, Ahi, Alo, true, akv_ln_g, akv_ln_b, 1);

    // attention
    softstats_k<<<64, 512>>>(Kh, mx, smv, ktv);
    ktv_k<<<dim3(8, 64), 256>>>(Kh, Vh, mx, smv, ktv);

    const long hs = 4096L * 64;
    dwconv_k<3, 0><<<dim3(512, 16), dim3(64, 8), 64 * 9 * 4>>>(
        Vh, 8 * hs, hs, 64, crpe, nullptr, nullptr, 8 * hs, hs, crpe_w3, 64, 2);
    dwconv_k<5, 0><<<dim3(512, 24), dim3(64, 8), 64 * 25 * 4>>>(
        Vh + 2 * hs, 8 * hs, hs, 64, crpe + 2 * hs, nullptr, nullptr, 8 * hs, hs,
        crpe_w5, 64, 3);
    dwconv_k<7, 0><<<dim3(512, 24), dim3(64, 8), 64 * 49 * 4>>>(
        Vh + 5 * hs, 8 * hs, hs, 64, crpe + 5 * hs, nullptr, nullptr, 8 * hs, hs,
        crpe_w7, 64, 3);

    // eff writes bf16 hi/lo directly into proj-A cols [0,512)
    eff_k<<<dim3(64, 64), 256>>>(Qh, ktv, crpe, Ahi, Alo);

    // projection: out = projA @ proj_w^T + proj_b
    mgemm_k<1><<<dim3(5, 256), 256, MG_SMEM>>>(Ahi, Alo, PWh, PWl, (float*)d_out, 640, 640,
                                               nullptr, proj_b, 0);
}